// round 7
// baseline (speedup 1.0000x reference)
#include <cuda_runtime.h>
#include <cuda_bf16.h>
#include <cstdint>

// Problem constants
#define NWIN   4096
#define NTOK   64
#define CDIM   192
#define NHEAD  6
#define HDIM   32
#define NMASK  64
#define MROWS  (NWIN * NTOK)          // 262144
#define SCALE_Q 0.17677669529663687f

#define OUT0_ELEMS  ((size_t)MROWS * CDIM)
#define ATTN_ELEMS  ((size_t)NWIN * NHEAD * NTOK * NTOK)

// ---------------- device scratch (allocation-free) ----------------
static __device__ float g_bias[NHEAD * NTOK * NTOK];

static __device__ __nv_bfloat16 g_ohi[MROWS * CDIM];
static __device__ __nv_bfloat16 g_olo[MROWS * CDIM];
static __device__ __nv_bfloat16 g_wq_hi[3 * CDIM * CDIM];
static __device__ __nv_bfloat16 g_wq_lo[3 * CDIM * CDIM];
static __device__ __nv_bfloat16 g_wp_hi[CDIM * CDIM];
static __device__ __nv_bfloat16 g_wp_lo[CDIM * CDIM];

// ---------------- helpers ----------------
__device__ __forceinline__ uint32_t smem_u32(const void* p) {
    uint32_t a;
    asm("{ .reg .u64 t; cvta.to.shared.u64 t, %1; cvt.u32.u64 %0, t; }" : "=r"(a) : "l"(p));
    return a;
}
__device__ __forceinline__ void ldsm4(uint32_t (&r)[4], uint32_t a) {
    asm volatile("ldmatrix.sync.aligned.m8n8.x4.shared.b16 {%0,%1,%2,%3}, [%4];"
                 : "=r"(r[0]), "=r"(r[1]), "=r"(r[2]), "=r"(r[3]) : "r"(a));
}
__device__ __forceinline__ void ldsm4t(uint32_t (&r)[4], uint32_t a) {
    asm volatile("ldmatrix.sync.aligned.m8n8.x4.trans.shared.b16 {%0,%1,%2,%3}, [%4];"
                 : "=r"(r[0]), "=r"(r[1]), "=r"(r[2]), "=r"(r[3]) : "r"(a));
}
__device__ __forceinline__ void mma16816(float (&d)[4], const uint32_t (&a)[4],
                                         uint32_t b0, uint32_t b1) {
    asm volatile("mma.sync.aligned.m16n8k16.row.col.f32.bf16.bf16.f32 "
                 "{%0,%1,%2,%3}, {%4,%5,%6,%7}, {%8,%9}, {%0,%1,%2,%3};"
                 : "+f"(d[0]), "+f"(d[1]), "+f"(d[2]), "+f"(d[3])
                 : "r"(a[0]), "r"(a[1]), "r"(a[2]), "r"(a[3]), "r"(b0), "r"(b1));
}
__device__ __forceinline__ uint32_t packbf(float a, float b) {
    __nv_bfloat162 t = __floats2bfloat162_rn(a, b);
    return *reinterpret_cast<uint32_t*>(&t);
}
__device__ __forceinline__ void split2(float a, float b, uint32_t& hi, uint32_t& lo) {
    __nv_bfloat16 ha = __float2bfloat16(a), hb = __float2bfloat16(b);
    float ra = a - __bfloat162float(ha);
    float rb = b - __bfloat162float(hb);
    __nv_bfloat162 th; th.x = ha; th.y = hb;
    hi = *reinterpret_cast<uint32_t*>(&th);
    lo = packbf(ra, rb);
}
__device__ __forceinline__ void cpasync16(uint32_t dst, const void* src) {
    asm volatile("cp.async.cg.shared.global [%0], [%1], 16;" :: "r"(dst), "l"(src));
}

// ---------------- bias gather ----------------
__global__ void bias_kernel(const float* __restrict__ table) {
    int e = blockIdx.x * 256 + threadIdx.x;
    int h  = e >> 12;
    int nm = e & 4095;
    int n = nm >> 6, m = nm & 63;
    int idx = ((n >> 3) - (m >> 3) + 7) * 15 + ((n & 7) - (m & 7) + 7);
    g_bias[e] = table[idx * NHEAD + h];
}

// ---------------- fp32 -> bf16 hi/lo split (weights only) ----------------
template<int DST>   // 1 = qkv_w, 2 = proj_w
__global__ void __launch_bounds__(256)
convert_kernel(const float* __restrict__ src, int n4) {
    int i = blockIdx.x * 256 + threadIdx.x;
    if (i >= n4) return;
    __nv_bfloat16* hi = (DST == 1) ? g_wq_hi : g_wp_hi;
    __nv_bfloat16* lo = (DST == 1) ? g_wq_lo : g_wp_lo;
    float4 v = reinterpret_cast<const float4*>(src)[i];
    uint32_t h0, h1, l0, l1;
    split2(v.x, v.y, h0, l0);
    split2(v.z, v.w, h1, l1);
    reinterpret_cast<uint2*>(hi)[i] = make_uint2(h0, h1);
    reinterpret_cast<uint2*>(lo)[i] = make_uint2(l0, l1);
}

// ================== FUSED QKV + ATTENTION (384 threads) ==================
// One CTA per window. Smem map (bytes):
//  [0, 49152)        A hi/lo (64x192 bf16 x2)  -> reused for V hi/lo
//  [49152, 122880)   B ring: 3 x 24576 (hi 12288 + lo 12288), 192x32 bf16
//  [122880, 172032)  Q hi/lo (per-head layout, 4096 B per head per part)
//  [172032, 221184)  K hi/lo
#define FA_HI 0
#define FA_LO 24576
#define FB    49152
#define FB_ST 24576
#define FQ_HI 122880
#define FQ_LO 147456
#define FK_HI 172032
#define FK_LO 196608
#define FV_HI 0
#define FV_LO 24576
#define FUSED_SMEM 221184
#define FTHREADS 384

__device__ __forceinline__ void issueB(uint32_t sb, int tid, int s, int kk, int buf) {
    uint32_t dstb = sb + FB + buf * FB_ST;
#pragma unroll
    for (int i = 0; i < 2; i++) {
        int idx = tid + i * FTHREADS;     // 0..767
        int row = idx >> 2, c = idx & 3;
        size_t src = (size_t)(s * CDIM + row) * CDIM + kk * 32 + c * 8;
        uint32_t d = dstb + row * 64 + ((c ^ ((row >> 1) & 3)) << 4);
        cpasync16(d,         g_wq_hi + src);
        cpasync16(d + 12288, g_wq_lo + src);
    }
    asm volatile("cp.async.commit_group;" ::: "memory");
}

__global__ void __launch_bounds__(FTHREADS, 1)
fused_kernel(const float* __restrict__ X, const float* __restrict__ qkv_b,
             const float* __restrict__ mask, float* __restrict__ attn_out) {
    extern __shared__ char sm[];
    const uint32_t sb = smem_u32(sm);
    const int tid = threadIdx.x;
    const int wid = tid >> 5, lane = tid & 31;
    const int b = blockIdx.x;
    const int mBase = b * 64;
    const int g = lane >> 3, rl = lane & 7;

    // prefetch W chunks 0,1
    issueB(sb, tid, 0, 0, 0);
    issueB(sb, tid, 0, 1, 1);

    // load A: 64 rows x 192 fp32 -> hi/lo bf16, swizzled (3 subtiles of 64 cols)
#pragma unroll
    for (int i = 0; i < 4; i++) {
        int idx = tid + i * FTHREADS;     // 0..1535
        int row = idx / 24, cc = idx % 24;
        const float* srcp = X + (size_t)(mBase + row) * CDIM + cc * 8;
        float4 f0 = *reinterpret_cast<const float4*>(srcp);
        float4 f1 = *reinterpret_cast<const float4*>(srcp + 4);
        uint32_t h0, h1, h2, h3, l0, l1, l2, l3;
        split2(f0.x, f0.y, h0, l0);
        split2(f0.z, f0.w, h1, l1);
        split2(f1.x, f1.y, h2, l2);
        split2(f1.z, f1.w, h3, l3);
        int sub = cc >> 3, ch = cc & 7;
        uint32_t d = row * 384 + sub * 128 + ((ch ^ (row & 7)) << 4);
        *reinterpret_cast<uint4*>(sm + FA_HI + d) = make_uint4(h0, h1, h2, h3);
        *reinterpret_cast<uint4*>(sm + FA_LO + d) = make_uint4(l0, l1, l2, l3);
    }

    // Phase-1 warp mapping: 12 warps = 4 M-groups x 3 N-groups, warp tile 16x64
    const int warpM = wid & 3;           // 0..3 -> rows warpM*16
    const int warpN = wid >> 2;          // 0..2 -> cols warpN*64
    const int aRow0 = warpM * 16 + ((g & 1) << 3) + rl;
    const int aChG  = g >> 1;
    const int bRow0 = warpN * 64 + ((g >> 1) << 3) + rl;
    const int bChG  = g & 1;

    float acc[8][4];

    // ---------------- Phase 1: QKV GEMM, 18 K32-chunks pipelined ----------------
    for (int cur = 0; cur < 18; cur++) {
        const int s = cur / 6, kk = cur % 6;
        if (kk == 0) {
#pragma unroll
            for (int b2 = 0; b2 < 8; b2++)
#pragma unroll
                for (int c = 0; c < 4; c++) acc[b2][c] = 0.0f;
        }
        if (cur < 17) { asm volatile("cp.async.wait_group 1;" ::: "memory"); }
        else          { asm volatile("cp.async.wait_group 0;" ::: "memory"); }
        __syncthreads();
        if (cur + 2 < 18) {
            int nxt = cur + 2;
            issueB(sb, tid, nxt / 6, nxt % 6, nxt % 3);
        }
        const uint32_t bufb = sb + FB + (cur % 3) * FB_ST;
        const int sub = kk >> 1;

#pragma unroll
        for (int ap = 0; ap < 2; ap++) {
            const uint32_t aB = sb + (ap ? FA_LO : FA_HI) + sub * 128;
#pragma unroll
            for (int ks = 0; ks < 2; ks++) {
                uint32_t af[4];
                const int chA = 2 * ((kk & 1) * 2 + ks) + aChG;
                {
                    int row = aRow0;
                    ldsm4(af, aB + row * 384 + ((chA ^ (row & 7)) << 4));
                }
#pragma unroll
                for (int bp = 0; bp < 2; bp++) {
                    if (ap == 1 && bp == 1) break;
                    const uint32_t bB = bufb + (bp ? 12288 : 0);
                    const int chB = 2 * ks + bChG;
#pragma unroll
                    for (int p = 0; p < 4; p++) {
                        uint32_t bf[4];
                        int row = bRow0 + p * 16;
                        ldsm4(bf, bB + row * 64 + ((chB ^ ((row >> 1) & 3)) << 4));
                        mma16816(acc[2 * p],     af, bf[0], bf[1]);
                        mma16816(acc[2 * p + 1], af, bf[2], bf[3]);
                    }
                }
            }
        }

        if (kk == 5) {
            // epilogue: write this s's 64x192 result into smem per-head layout
            if (s == 2) __syncthreads();    // all warps done reading A before V overwrite
            const float sc = (s == 0) ? SCALE_Q : 1.0f;
            const uint32_t dh = (s == 0) ? FQ_HI : (s == 1) ? FK_HI : FV_HI;
            const uint32_t dl = (s == 0) ? FQ_LO : (s == 1) ? FK_LO : FV_LO;
#pragma unroll
            for (int nt = 0; nt < 8; nt++) {
                int col = warpN * 64 + nt * 8 + (lane & 3) * 2;
                float b0 = qkv_b[s * CDIM + col];
                float b1 = qkv_b[s * CDIM + col + 1];
                int hh = col >> 5, d = col & 31;
#pragma unroll
                for (int rh = 0; rh < 2; rh++) {
                    int t = warpM * 16 + (lane >> 2) + rh * 8;
                    float v0 = (acc[nt][2 * rh + 0] + b0) * sc;
                    float v1 = (acc[nt][2 * rh + 1] + b1) * sc;
                    uint32_t hi, lo;
                    split2(v0, v1, hi, lo);
                    uint32_t off = hh * 4096 + t * 64 +
                                   (((d >> 3) ^ ((t >> 1) & 3)) << 4) + (d & 7) * 2;
                    *reinterpret_cast<uint32_t*>(sm + dh + off) = hi;
                    *reinterpret_cast<uint32_t*>(sm + dl + off) = lo;
                }
            }
        }
    }
    __syncthreads();

    // ---------------- Phase 2: attention, 3 teams x 2 iterations = 6 heads -----
    const int team = wid >> 2;           // 0..2
    const int wrow = wid & 3;            // row group within team
    const int r0 = wrow * 16 + (lane >> 2);
    const int q2 = (lane & 3) * 2;
    const float* mp = mask + ((size_t)(b & (NMASK - 1)) << 12);

#pragma unroll
    for (int it = 0; it < 2; it++) {
        const int h = it * 3 + team;
        const uint32_t qoff = h * 4096;

        // S = Q K^T, 3-pass hi/lo
        float S[8][4];
#pragma unroll
        for (int t = 0; t < 8; t++)
#pragma unroll
            for (int j = 0; j < 4; j++) S[t][j] = 0.0f;

#pragma unroll
        for (int pass = 0; pass < 3; pass++) {
            const uint32_t qb = sb + ((pass == 2) ? FQ_LO : FQ_HI) + qoff;
            const uint32_t kb = sb + ((pass == 1) ? FK_LO : FK_HI) + qoff;
#pragma unroll
            for (int ks = 0; ks < 2; ks++) {
                uint32_t af[4];
                {
                    int row = wrow * 16 + ((g & 1) << 3) + rl;
                    int c = (2 * ks + (g >> 1)) ^ ((row >> 1) & 3);
                    ldsm4(af, qb + row * 64 + (c << 4));
                }
#pragma unroll
                for (int nt2 = 0; nt2 < 4; nt2++) {
                    uint32_t bf[4];
                    {
                        int row = nt2 * 16 + ((g >> 1) << 3) + rl;
                        int c = (2 * ks + (g & 1)) ^ ((row >> 1) & 3);
                        ldsm4(bf, kb + row * 64 + (c << 4));
                    }
                    mma16816(S[2 * nt2],     af, bf[0], bf[1]);
                    mma16816(S[2 * nt2 + 1], af, bf[2], bf[3]);
                }
            }
        }

        // bias + mask (from L2) + softmax on fragments
        const float* bp = g_bias + ((size_t)h << 12);
        float mlo = -1e30f, mhi = -1e30f;
#pragma unroll
        for (int t = 0; t < 8; t++) {
            int cc = 8 * t + q2;
            float2 b0 = *reinterpret_cast<const float2*>(bp + r0 * 64 + cc);
            float2 b1 = *reinterpret_cast<const float2*>(bp + (r0 + 8) * 64 + cc);
            float2 m0 = *reinterpret_cast<const float2*>(mp + r0 * 64 + cc);
            float2 m1 = *reinterpret_cast<const float2*>(mp + (r0 + 8) * 64 + cc);
            S[t][0] += b0.x + m0.x; S[t][1] += b0.y + m0.y;
            S[t][2] += b1.x + m1.x; S[t][3] += b1.y + m1.y;
            mlo = fmaxf(mlo, fmaxf(S[t][0], S[t][1]));
            mhi = fmaxf(mhi, fmaxf(S[t][2], S[t][3]));
        }
#pragma unroll
        for (int off = 1; off < 4; off <<= 1) {
            mlo = fmaxf(mlo, __shfl_xor_sync(0xffffffffu, mlo, off));
            mhi = fmaxf(mhi, __shfl_xor_sync(0xffffffffu, mhi, off));
        }
        float slo = 0.0f, shi = 0.0f;
#pragma unroll
        for (int t = 0; t < 8; t++) {
            S[t][0] = __expf(S[t][0] - mlo); S[t][1] = __expf(S[t][1] - mlo);
            S[t][2] = __expf(S[t][2] - mhi); S[t][3] = __expf(S[t][3] - mhi);
            slo += S[t][0] + S[t][1];
            shi += S[t][2] + S[t][3];
        }
#pragma unroll
        for (int off = 1; off < 4; off <<= 1) {
            slo += __shfl_xor_sync(0xffffffffu, slo, off);
            shi += __shfl_xor_sync(0xffffffffu, shi, off);
        }
        const float ilo = 1.0f / slo, ihi = 1.0f / shi;

        // normalize, write attn, build P fragments (hi/lo)
        const size_t ab = ((size_t)b * NHEAD + h) << 12;
        uint32_t Ph[4][4], Pl[4][4];
#pragma unroll
        for (int t = 0; t < 8; t++) {
            S[t][0] *= ilo; S[t][1] *= ilo;
            S[t][2] *= ihi; S[t][3] *= ihi;
            *reinterpret_cast<float2*>(attn_out + ab + (size_t)r0 * 64 + 8 * t + q2)
                = make_float2(S[t][0], S[t][1]);
            *reinterpret_cast<float2*>(attn_out + ab + (size_t)(r0 + 8) * 64 + 8 * t + q2)
                = make_float2(S[t][2], S[t][3]);
        }
#pragma unroll
        for (int kt = 0; kt < 4; kt++) {
            split2(S[2 * kt][0],     S[2 * kt][1],     Ph[kt][0], Pl[kt][0]);
            split2(S[2 * kt][2],     S[2 * kt][3],     Ph[kt][1], Pl[kt][1]);
            split2(S[2 * kt + 1][0], S[2 * kt + 1][1], Ph[kt][2], Pl[kt][2]);
            split2(S[2 * kt + 1][2], S[2 * kt + 1][3], Ph[kt][3], Pl[kt][3]);
        }

        // O = P V, 3-pass hi/lo, V via ldmatrix.trans (V lives in old A region)
        float O[4][4];
#pragma unroll
        for (int t = 0; t < 4; t++)
#pragma unroll
            for (int j = 0; j < 4; j++) O[t][j] = 0.0f;

#pragma unroll
        for (int pass = 0; pass < 3; pass++) {
            const uint32_t vb = sb + ((pass == 1) ? FV_LO : FV_HI) + qoff;
#pragma unroll
            for (int kt = 0; kt < 4; kt++) {
                const uint32_t (&af)[4] = (pass == 2) ? Pl[kt] : Ph[kt];
#pragma unroll
                for (int nt2 = 0; nt2 < 2; nt2++) {
                    uint32_t bf[4];
                    int row = kt * 16 + ((g & 1) << 3) + rl;
                    int c = (2 * nt2 + (g >> 1)) ^ ((row >> 1) & 3);
                    ldsm4t(bf, vb + row * 64 + (c << 4));
                    mma16816(O[2 * nt2],     af, bf[0], bf[1]);
                    mma16816(O[2 * nt2 + 1], af, bf[2], bf[3]);
                }
            }
        }

        // write O as bf16 hi/lo, layout [b][tok][h*32+d]
        const size_t ob = (size_t)b * NTOK * CDIM + h * HDIM;
#pragma unroll
        for (int dt = 0; dt < 4; dt++) {
            int col = 8 * dt + q2;
            uint32_t hi0, lo0, hi1, lo1;
            split2(O[dt][0], O[dt][1], hi0, lo0);
            split2(O[dt][2], O[dt][3], hi1, lo1);
            *reinterpret_cast<uint32_t*>(g_ohi + ob + (size_t)r0 * CDIM + col)       = hi0;
            *reinterpret_cast<uint32_t*>(g_olo + ob + (size_t)r0 * CDIM + col)       = lo0;
            *reinterpret_cast<uint32_t*>(g_ohi + ob + (size_t)(r0 + 8) * CDIM + col) = hi1;
            *reinterpret_cast<uint32_t*>(g_olo + ob + (size_t)(r0 + 8) * CDIM + col) = lo1;
        }
    }
}

// ---------------- proj GEMM (unchanged) ----------------
#define SMA_HI 0
#define SMA_LO 8192
#define SMB_HI 16384
#define SMB_LO 40960
#define GEMM_SMEM 65536

__global__ void __launch_bounds__(256, 2)
proj_gemm(const float* __restrict__ bias, float* __restrict__ out) {
    extern __shared__ char sm[];
    const int tid = threadIdx.x;
    const int wid = tid >> 5, lane = tid & 31;
    const int mBase = blockIdx.y * 64;

    const uint32_t sb = smem_u32(sm);

    float acc[2][6][4];
#pragma unroll
    for (int a = 0; a < 2; a++)
#pragma unroll
        for (int b = 0; b < 6; b++)
#pragma unroll
            for (int c = 0; c < 4; c++) acc[a][b][c] = 0.0f;

    const int g  = lane >> 3, rl = lane & 7;
    const int aRow0 = (wid >> 2) * 32 + ((g & 1) << 3) + rl;
    const int aChG  = g >> 1;
    const int bRow0 = (wid & 3) * 48 + ((g >> 1) << 3) + rl;
    const int bChG  = g & 1;

    for (int kc = 0; kc < 3; kc++) {
#pragma unroll
        for (int i = 0; i < 2; i++) {
            int idx = tid + i * 256;
            int row = idx >> 3, ch = idx & 7;
            size_t src = (size_t)(mBase + row) * CDIM + kc * 64 + ch * 8;
            uint32_t dst = row * 128 + ((ch ^ (row & 7)) << 4);
            *reinterpret_cast<uint4*>(sm + SMA_HI + dst) =
                *reinterpret_cast<const uint4*>(g_ohi + src);
            *reinterpret_cast<uint4*>(sm + SMA_LO + dst) =
                *reinterpret_cast<const uint4*>(g_olo + src);
        }
#pragma unroll
        for (int i = 0; i < 6; i++) {
            int idx = tid + i * 256;
            int row = idx >> 3, ch = idx & 7;
            size_t src = (size_t)row * CDIM + kc * 64 + ch * 8;
            uint32_t dst = row * 128 + ((ch ^ (row & 7)) << 4);
            *reinterpret_cast<uint4*>(sm + SMB_HI + dst) =
                *reinterpret_cast<const uint4*>(g_wp_hi + src);
            *reinterpret_cast<uint4*>(sm + SMB_LO + dst) =
                *reinterpret_cast<const uint4*>(g_wp_lo + src);
        }
        __syncthreads();

#pragma unroll
        for (int ap = 0; ap < 2; ap++) {
            const uint32_t aB = sb + (ap ? SMA_LO : SMA_HI);
#pragma unroll
            for (int ks = 0; ks < 4; ks++) {
                uint32_t af[2][4];
#pragma unroll
                for (int mt = 0; mt < 2; mt++) {
                    int row = aRow0 + mt * 16;
                    int ch  = 2 * ks + aChG;
                    ldsm4(af[mt], aB + row * 128 + ((ch ^ (row & 7)) << 4));
                }
#pragma unroll
                for (int bp = 0; bp < 2; bp++) {
                    if (ap == 1 && bp == 1) break;
                    const uint32_t bB = sb + (bp ? SMB_LO : SMB_HI);
#pragma unroll
                    for (int p = 0; p < 3; p++) {
                        uint32_t bf[4];
                        int row = bRow0 + p * 16;
                        int ch  = 2 * ks + bChG;
                        ldsm4(bf, bB + row * 128 + ((ch ^ (row & 7)) << 4));
#pragma unroll
                        for (int mt = 0; mt < 2; mt++) {
                            mma16816(acc[mt][2 * p],     af[mt], bf[0], bf[1]);
                            mma16816(acc[mt][2 * p + 1], af[mt], bf[2], bf[3]);
                        }
                    }
                }
            }
        }
        __syncthreads();
    }

#pragma unroll
    for (int mt = 0; mt < 2; mt++) {
#pragma unroll
        for (int nt = 0; nt < 6; nt++) {
            int col = (wid & 3) * 48 + nt * 8 + (lane & 3) * 2;
            float b0 = bias[col];
            float b1 = bias[col + 1];
#pragma unroll
            for (int rh = 0; rh < 2; rh++) {
                int t = (wid >> 2) * 32 + mt * 16 + (lane >> 2) + rh * 8;
                float v0 = acc[mt][nt][2 * rh + 0] + b0;
                float v1 = acc[mt][nt][2 * rh + 1] + b1;
                *reinterpret_cast<float2*>(out + (size_t)(mBase + t) * CDIM + col)
                    = make_float2(v0, v1);
            }
        }
    }
}

// ---------------------------------------------------------------------------
extern "C" void kernel_launch(void* const* d_in, const int* in_sizes, int n_in,
                              void* d_out, int out_size) {
    const float* x      = (const float*)d_in[0];
    const float* mask   = (const float*)d_in[1];
    const float* qkv_w  = (const float*)d_in[2];
    const float* qkv_b  = (const float*)d_in[3];
    const float* proj_w = (const float*)d_in[4];
    const float* proj_b = (const float*)d_in[5];
    const float* table  = (const float*)d_in[6];

    float* out = (float*)d_out;
    float* attn_out = out + OUT0_ELEMS;

    cudaFuncSetAttribute(fused_kernel, cudaFuncAttributeMaxDynamicSharedMemorySize, FUSED_SMEM);
    cudaFuncSetAttribute(proj_gemm, cudaFuncAttributeMaxDynamicSharedMemorySize, GEMM_SMEM);

    // 1) bias gather + weight hi/lo conversions
    bias_kernel<<<96, 256>>>(table);
    {
        int w4 = (3 * CDIM * CDIM) / 4;
        convert_kernel<1><<<(w4 + 255) / 256, 256>>>(qkv_w, w4);
        int p4 = (CDIM * CDIM) / 4;
        convert_kernel<2><<<(p4 + 255) / 256, 256>>>(proj_w, p4);
    }

    // 2) fused QKV + attention: writes attn (fp32) + O (bf16 hi/lo)
    fused_kernel<<<NWIN, FTHREADS, FUSED_SMEM>>>(x, qkv_b, mask, attn_out);

    // 3) output projection
    proj_gemm<<<dim3(1, NWIN), 256, GEMM_SMEM>>>(proj_b, out);

    (void)in_sizes; (void)n_in; (void)out_size;
}

// round 8
// speedup vs baseline: 1.3843x; 1.3843x over previous
#include <cuda_runtime.h>
#include <cuda_fp16.h>
#include <cstdint>

// Problem constants
#define NWIN   4096
#define NTOK   64
#define CDIM   192
#define NHEAD  6
#define HDIM   32
#define NMASK  64
#define MROWS  (NWIN * NTOK)          // 262144
#define SCALE_Q 0.17677669529663687f

#define OUT0_ELEMS  ((size_t)MROWS * CDIM)
#define ATTN_ELEMS  ((size_t)NWIN * NHEAD * NTOK * NTOK)

// ---------------- device scratch (allocation-free) ----------------
static __device__ float g_bias[NHEAD * NTOK * NTOK];

static __device__ __half g_ohi[MROWS * CDIM];        // attn output, fp16 hi/lo
static __device__ __half g_olo[MROWS * CDIM];
static __device__ __half g_wq[3 * CDIM * CDIM];      // weights, single fp16
static __device__ __half g_wp[CDIM * CDIM];

// ---------------- helpers ----------------
__device__ __forceinline__ uint32_t smem_u32(const void* p) {
    uint32_t a;
    asm("{ .reg .u64 t; cvta.to.shared.u64 t, %1; cvt.u32.u64 %0, t; }" : "=r"(a) : "l"(p));
    return a;
}
__device__ __forceinline__ void ldsm4(uint32_t (&r)[4], uint32_t a) {
    asm volatile("ldmatrix.sync.aligned.m8n8.x4.shared.b16 {%0,%1,%2,%3}, [%4];"
                 : "=r"(r[0]), "=r"(r[1]), "=r"(r[2]), "=r"(r[3]) : "r"(a));
}
__device__ __forceinline__ void ldsm4t(uint32_t (&r)[4], uint32_t a) {
    asm volatile("ldmatrix.sync.aligned.m8n8.x4.trans.shared.b16 {%0,%1,%2,%3}, [%4];"
                 : "=r"(r[0]), "=r"(r[1]), "=r"(r[2]), "=r"(r[3]) : "r"(a));
}
__device__ __forceinline__ void mma16816(float (&d)[4], const uint32_t (&a)[4],
                                         uint32_t b0, uint32_t b1) {
    asm volatile("mma.sync.aligned.m16n8k16.row.col.f32.f16.f16.f32 "
                 "{%0,%1,%2,%3}, {%4,%5,%6,%7}, {%8,%9}, {%0,%1,%2,%3};"
                 : "+f"(d[0]), "+f"(d[1]), "+f"(d[2]), "+f"(d[3])
                 : "r"(a[0]), "r"(a[1]), "r"(a[2]), "r"(a[3]), "r"(b0), "r"(b1));
}
__device__ __forceinline__ uint32_t packh(float a, float b) {
    __half2 t = __floats2half2_rn(a, b);
    return *reinterpret_cast<uint32_t*>(&t);
}
// fp16 hi/lo split of a float pair
__device__ __forceinline__ void split2h(float a, float b, uint32_t& hi, uint32_t& lo) {
    __half ha = __float2half_rn(a), hb = __float2half_rn(b);
    float ra = a - __half2float(ha);
    float rb = b - __half2float(hb);
    __half2 th = __halves2half2(ha, hb);
    hi = *reinterpret_cast<uint32_t*>(&th);
    lo = packh(ra, rb);
}
__device__ __forceinline__ void cpasync16(uint32_t dst, const void* src) {
    asm volatile("cp.async.cg.shared.global [%0], [%1], 16;" :: "r"(dst), "l"(src));
}

// ---------------- bias gather ----------------
__global__ void bias_kernel(const float* __restrict__ table) {
    int e = blockIdx.x * 256 + threadIdx.x;
    int h  = e >> 12;
    int nm = e & 4095;
    int n = nm >> 6, m = nm & 63;
    int idx = ((n >> 3) - (m >> 3) + 7) * 15 + ((n & 7) - (m & 7) + 7);
    g_bias[e] = table[idx * NHEAD + h];
}

// ---------------- fp32 -> single fp16 (weights) ----------------
template<int DST>   // 1 = qkv_w, 2 = proj_w
__global__ void __launch_bounds__(256)
convert_kernel(const float* __restrict__ src, int n4) {
    int i = blockIdx.x * 256 + threadIdx.x;
    if (i >= n4) return;
    __half* dst = (DST == 1) ? g_wq : g_wp;
    float4 v = reinterpret_cast<const float4*>(src)[i];
    reinterpret_cast<uint2*>(dst)[i] =
        make_uint2(packh(v.x, v.y), packh(v.z, v.w));
}

// ================== FUSED QKV + ATTENTION (256 threads) ==================
// Smem map (bytes):
//  [0, 49152)        A hi/lo (64x192 fp16 x2) -> hi region reused for V (single)
//  [49152, 86016)    B ring: 3 x 12288, 192x32 fp16 (single)
//  [86016, 135168)   Q hi/lo (per-head layout: 4096 B per head per part)
//  [135168, 159744)  K (single, per-head layout)
#define FA_HI 0
#define FA_LO 24576
#define FB    49152
#define FB_ST 12288
#define FQ_HI 86016
#define FQ_LO 110592
#define FK    135168
#define FV    0
#define FUSED_SMEM 159744

__device__ __forceinline__ void issueB(uint32_t sb, int tid, int s, int kk, int buf) {
    uint32_t dstb = sb + FB + buf * FB_ST;
#pragma unroll
    for (int i = 0; i < 3; i++) {
        int idx = tid + i * 256;          // 0..767
        int row = idx >> 2, c = idx & 3;
        size_t src = (size_t)(s * CDIM + row) * CDIM + kk * 32 + c * 8;
        cpasync16(dstb + row * 64 + ((c ^ ((row >> 1) & 3)) << 4), g_wq + src);
    }
    asm volatile("cp.async.commit_group;" ::: "memory");
}

__global__ void __launch_bounds__(256, 1)
fused_kernel(const float* __restrict__ X, const float* __restrict__ qkv_b,
             const float* __restrict__ mask, float* __restrict__ attn_out) {
    extern __shared__ char sm[];
    const uint32_t sb = smem_u32(sm);
    const int tid = threadIdx.x;
    const int wid = tid >> 5, lane = tid & 31;
    const int b = blockIdx.x;
    const int mBase = b * 64;
    const int g = lane >> 3, rl = lane & 7;

    // prefetch W chunks 0,1
    issueB(sb, tid, 0, 0, 0);
    issueB(sb, tid, 0, 1, 1);

    // load A: 64 rows x 192 fp32 -> fp16 hi/lo, swizzled (3 subtiles of 64 cols)
#pragma unroll
    for (int i = 0; i < 6; i++) {
        int idx = tid + i * 256;          // 0..1535
        int row = idx / 24, cc = idx % 24;
        const float* srcp = X + (size_t)(mBase + row) * CDIM + cc * 8;
        float4 f0 = *reinterpret_cast<const float4*>(srcp);
        float4 f1 = *reinterpret_cast<const float4*>(srcp + 4);
        uint32_t h0, h1, h2, h3, l0, l1, l2, l3;
        split2h(f0.x, f0.y, h0, l0);
        split2h(f0.z, f0.w, h1, l1);
        split2h(f1.x, f1.y, h2, l2);
        split2h(f1.z, f1.w, h3, l3);
        int sub = cc >> 3, ch = cc & 7;
        uint32_t d = row * 384 + sub * 128 + ((ch ^ (row & 7)) << 4);
        *reinterpret_cast<uint4*>(sm + FA_HI + d) = make_uint4(h0, h1, h2, h3);
        *reinterpret_cast<uint4*>(sm + FA_LO + d) = make_uint4(l0, l1, l2, l3);
    }

    // Phase-1 warp mapping: 8 warps, warp tile 32(M) x 48(N)
    const int aRow0 = (wid >> 2) * 32 + ((g & 1) << 3) + rl;
    const int aChG  = g >> 1;
    const int bRow0 = (wid & 3) * 48 + ((g >> 1) << 3) + rl;
    const int bChG  = g & 1;

    float acc[2][6][4];

    // ---------------- Phase 1: QKV GEMM, 18 K32-chunks pipelined ----------------
    for (int cur = 0; cur < 18; cur++) {
        const int s = cur / 6, kk = cur % 6;
        if (kk == 0) {
#pragma unroll
            for (int a = 0; a < 2; a++)
#pragma unroll
                for (int b2 = 0; b2 < 6; b2++)
#pragma unroll
                    for (int c = 0; c < 4; c++) acc[a][b2][c] = 0.0f;
        }
        if (cur < 17) { asm volatile("cp.async.wait_group 1;" ::: "memory"); }
        else          { asm volatile("cp.async.wait_group 0;" ::: "memory"); }
        __syncthreads();
        if (cur + 2 < 18) {
            int nxt = cur + 2;
            issueB(sb, tid, nxt / 6, nxt % 6, nxt % 3);
        }
        const uint32_t bufb = sb + FB + (cur % 3) * FB_ST;
        const int sub = kk >> 1;

#pragma unroll
        for (int ks = 0; ks < 2; ks++) {
            // A fragments: hi and lo (B loaded once, reused for both passes)
            uint32_t afh[2][4], afl[2][4];
            const int chA = 2 * ((kk & 1) * 2 + ks) + aChG;
#pragma unroll
            for (int mt = 0; mt < 2; mt++) {
                int row = aRow0 + mt * 16;
                uint32_t ao = row * 384 + sub * 128 + ((chA ^ (row & 7)) << 4);
                ldsm4(afh[mt], sb + FA_HI + ao);
                ldsm4(afl[mt], sb + FA_LO + ao);
            }
            const int chB = 2 * ks + bChG;
#pragma unroll
            for (int p = 0; p < 3; p++) {
                uint32_t bf[4];
                int row = bRow0 + p * 16;
                ldsm4(bf, bufb + row * 64 + ((chB ^ ((row >> 1) & 3)) << 4));
#pragma unroll
                for (int mt = 0; mt < 2; mt++) {
                    mma16816(acc[mt][2 * p],     afh[mt], bf[0], bf[1]);
                    mma16816(acc[mt][2 * p + 1], afh[mt], bf[2], bf[3]);
                    mma16816(acc[mt][2 * p],     afl[mt], bf[0], bf[1]);
                    mma16816(acc[mt][2 * p + 1], afl[mt], bf[2], bf[3]);
                }
            }
        }

        if (kk == 5) {
            // epilogue: write this s's 64x192 into smem per-head layout
            if (s == 2) __syncthreads();    // all warps done reading A before V overwrite
            const float sc = (s == 0) ? SCALE_Q : 1.0f;
#pragma unroll
            for (int mt = 0; mt < 2; mt++) {
#pragma unroll
                for (int nt = 0; nt < 6; nt++) {
                    int col = (wid & 3) * 48 + nt * 8 + (lane & 3) * 2;
                    float b0 = qkv_b[s * CDIM + col];
                    float b1 = qkv_b[s * CDIM + col + 1];
                    int hh = col >> 5, d = col & 31;
#pragma unroll
                    for (int rh = 0; rh < 2; rh++) {
                        int t = (wid >> 2) * 32 + mt * 16 + (lane >> 2) + rh * 8;
                        float v0 = (acc[mt][nt][2 * rh + 0] + b0) * sc;
                        float v1 = (acc[mt][nt][2 * rh + 1] + b1) * sc;
                        uint32_t off = hh * 4096 + t * 64 +
                                       (((d >> 3) ^ ((t >> 1) & 3)) << 4) + (d & 7) * 2;
                        if (s == 0) {
                            uint32_t hi, lo;
                            split2h(v0, v1, hi, lo);
                            *reinterpret_cast<uint32_t*>(sm + FQ_HI + off) = hi;
                            *reinterpret_cast<uint32_t*>(sm + FQ_LO + off) = lo;
                        } else {
                            uint32_t hv = packh(v0, v1);
                            *reinterpret_cast<uint32_t*>(sm + (s == 1 ? FK : FV) + off) = hv;
                        }
                    }
                }
            }
        }
    }
    __syncthreads();

    // ---------------- Phase 2: attention, 2 teams x 3 iterations = 6 heads -----
    const int team = wid >> 2;           // 0..1
    const int wrow = wid & 3;
    const int r0 = wrow * 16 + (lane >> 2);
    const int q2 = (lane & 3) * 2;
    const float* mp = mask + ((size_t)(b & (NMASK - 1)) << 12);

#pragma unroll
    for (int it = 0; it < 3; it++) {
        const int h = 2 * it + team;
        const uint32_t qoff = h * 4096;

        // S = Q K^T: 2 passes (Q hi/lo x K single)
        float S[8][4];
#pragma unroll
        for (int t = 0; t < 8; t++)
#pragma unroll
            for (int j = 0; j < 4; j++) S[t][j] = 0.0f;

#pragma unroll
        for (int pass = 0; pass < 2; pass++) {
            const uint32_t qb = sb + (pass ? FQ_LO : FQ_HI) + qoff;
            const uint32_t kb = sb + FK + qoff;
#pragma unroll
            for (int ks = 0; ks < 2; ks++) {
                uint32_t af[4];
                {
                    int row = wrow * 16 + ((g & 1) << 3) + rl;
                    int c = (2 * ks + (g >> 1)) ^ ((row >> 1) & 3);
                    ldsm4(af, qb + row * 64 + (c << 4));
                }
#pragma unroll
                for (int nt2 = 0; nt2 < 4; nt2++) {
                    uint32_t bf[4];
                    {
                        int row = nt2 * 16 + ((g >> 1) << 3) + rl;
                        int c = (2 * ks + (g & 1)) ^ ((row >> 1) & 3);
                        ldsm4(bf, kb + row * 64 + (c << 4));
                    }
                    mma16816(S[2 * nt2],     af, bf[0], bf[1]);
                    mma16816(S[2 * nt2 + 1], af, bf[2], bf[3]);
                }
            }
        }

        // bias + mask + softmax on fragments
        const float* bp = g_bias + ((size_t)h << 12);
        float mlo = -1e30f, mhi = -1e30f;
#pragma unroll
        for (int t = 0; t < 8; t++) {
            int cc = 8 * t + q2;
            float2 b0 = *reinterpret_cast<const float2*>(bp + r0 * 64 + cc);
            float2 b1 = *reinterpret_cast<const float2*>(bp + (r0 + 8) * 64 + cc);
            float2 m0 = *reinterpret_cast<const float2*>(mp + r0 * 64 + cc);
            float2 m1 = *reinterpret_cast<const float2*>(mp + (r0 + 8) * 64 + cc);
            S[t][0] += b0.x + m0.x; S[t][1] += b0.y + m0.y;
            S[t][2] += b1.x + m1.x; S[t][3] += b1.y + m1.y;
            mlo = fmaxf(mlo, fmaxf(S[t][0], S[t][1]));
            mhi = fmaxf(mhi, fmaxf(S[t][2], S[t][3]));
        }
#pragma unroll
        for (int off = 1; off < 4; off <<= 1) {
            mlo = fmaxf(mlo, __shfl_xor_sync(0xffffffffu, mlo, off));
            mhi = fmaxf(mhi, __shfl_xor_sync(0xffffffffu, mhi, off));
        }
        float slo = 0.0f, shi = 0.0f;
#pragma unroll
        for (int t = 0; t < 8; t++) {
            S[t][0] = __expf(S[t][0] - mlo); S[t][1] = __expf(S[t][1] - mlo);
            S[t][2] = __expf(S[t][2] - mhi); S[t][3] = __expf(S[t][3] - mhi);
            slo += S[t][0] + S[t][1];
            shi += S[t][2] + S[t][3];
        }
#pragma unroll
        for (int off = 1; off < 4; off <<= 1) {
            slo += __shfl_xor_sync(0xffffffffu, slo, off);
            shi += __shfl_xor_sync(0xffffffffu, shi, off);
        }
        const float ilo = 1.0f / slo, ihi = 1.0f / shi;

        // normalize, write attn, build P fragments (fp16 hi/lo)
        const size_t ab = ((size_t)b * NHEAD + h) << 12;
        uint32_t Ph[4][4], Pl[4][4];
#pragma unroll
        for (int t = 0; t < 8; t++) {
            S[t][0] *= ilo; S[t][1] *= ilo;
            S[t][2] *= ihi; S[t][3] *= ihi;
            *reinterpret_cast<float2*>(attn_out + ab + (size_t)r0 * 64 + 8 * t + q2)
                = make_float2(S[t][0], S[t][1]);
            *reinterpret_cast<float2*>(attn_out + ab + (size_t)(r0 + 8) * 64 + 8 * t + q2)
                = make_float2(S[t][2], S[t][3]);
        }
#pragma unroll
        for (int kt = 0; kt < 4; kt++) {
            split2h(S[2 * kt][0],     S[2 * kt][1],     Ph[kt][0], Pl[kt][0]);
            split2h(S[2 * kt][2],     S[2 * kt][3],     Ph[kt][1], Pl[kt][1]);
            split2h(S[2 * kt + 1][0], S[2 * kt + 1][1], Ph[kt][2], Pl[kt][2]);
            split2h(S[2 * kt + 1][2], S[2 * kt + 1][3], Ph[kt][3], Pl[kt][3]);
        }

        // O = P V: 2 passes (P hi/lo x V single), V via ldmatrix.trans
        float O[4][4];
#pragma unroll
        for (int t = 0; t < 4; t++)
#pragma unroll
            for (int j = 0; j < 4; j++) O[t][j] = 0.0f;

        const uint32_t vb = sb + FV + qoff;
#pragma unroll
        for (int kt = 0; kt < 4; kt++) {
#pragma unroll
            for (int nt2 = 0; nt2 < 2; nt2++) {
                uint32_t bf[4];
                int row = kt * 16 + ((g & 1) << 3) + rl;
                int c = (2 * nt2 + (g >> 1)) ^ ((row >> 1) & 3);
                ldsm4t(bf, vb + row * 64 + (c << 4));
                mma16816(O[2 * nt2],     Ph[kt], bf[0], bf[1]);
                mma16816(O[2 * nt2 + 1], Ph[kt], bf[2], bf[3]);
                mma16816(O[2 * nt2],     Pl[kt], bf[0], bf[1]);
                mma16816(O[2 * nt2 + 1], Pl[kt], bf[2], bf[3]);
            }
        }

        // write O as fp16 hi/lo, layout [b][tok][h*32+d]
        const size_t ob = (size_t)b * NTOK * CDIM + h * HDIM;
#pragma unroll
        for (int dt = 0; dt < 4; dt++) {
            int col = 8 * dt + q2;
            uint32_t hi0, lo0, hi1, lo1;
            split2h(O[dt][0], O[dt][1], hi0, lo0);
            split2h(O[dt][2], O[dt][3], hi1, lo1);
            *reinterpret_cast<uint32_t*>(g_ohi + ob + (size_t)r0 * CDIM + col)       = hi0;
            *reinterpret_cast<uint32_t*>(g_olo + ob + (size_t)r0 * CDIM + col)       = lo0;
            *reinterpret_cast<uint32_t*>(g_ohi + ob + (size_t)(r0 + 8) * CDIM + col) = hi1;
            *reinterpret_cast<uint32_t*>(g_olo + ob + (size_t)(r0 + 8) * CDIM + col) = lo1;
        }
    }
}

// ---------------- proj GEMM: O (fp16 hi/lo) x Wp (fp16 single) ----------------
#define SMA_HI 0
#define SMA_LO 8192
#define SMB    16384
#define GEMM_SMEM 40960

__global__ void __launch_bounds__(256, 3)
proj_gemm(const float* __restrict__ bias, float* __restrict__ out) {
    extern __shared__ char sm[];
    const int tid = threadIdx.x;
    const int wid = tid >> 5, lane = tid & 31;
    const int mBase = blockIdx.y * 64;

    const uint32_t sb = smem_u32(sm);

    float acc[2][6][4];
#pragma unroll
    for (int a = 0; a < 2; a++)
#pragma unroll
        for (int b = 0; b < 6; b++)
#pragma unroll
            for (int c = 0; c < 4; c++) acc[a][b][c] = 0.0f;

    const int g  = lane >> 3, rl = lane & 7;
    const int aRow0 = (wid >> 2) * 32 + ((g & 1) << 3) + rl;
    const int aChG  = g >> 1;
    const int bRow0 = (wid & 3) * 48 + ((g >> 1) << 3) + rl;
    const int bChG  = g & 1;

    for (int kc = 0; kc < 3; kc++) {
        // A: 64 rows x 64 fp16 (hi+lo)
#pragma unroll
        for (int i = 0; i < 2; i++) {
            int idx = tid + i * 256;      // 0..511
            int row = idx >> 3, ch = idx & 7;
            size_t src = (size_t)(mBase + row) * CDIM + kc * 64 + ch * 8;
            uint32_t dst = row * 128 + ((ch ^ (row & 7)) << 4);
            *reinterpret_cast<uint4*>(sm + SMA_HI + dst) =
                *reinterpret_cast<const uint4*>(g_ohi + src);
            *reinterpret_cast<uint4*>(sm + SMA_LO + dst) =
                *reinterpret_cast<const uint4*>(g_olo + src);
        }
        // B: 192 rows x 64 fp16 (single)
#pragma unroll
        for (int i = 0; i < 6; i++) {
            int idx = tid + i * 256;      // 0..1535
            int row = idx >> 3, ch = idx & 7;
            size_t src = (size_t)row * CDIM + kc * 64 + ch * 8;
            uint32_t dst = row * 128 + ((ch ^ (row & 7)) << 4);
            *reinterpret_cast<uint4*>(sm + SMB + dst) =
                *reinterpret_cast<const uint4*>(g_wp + src);
        }
        __syncthreads();

#pragma unroll
        for (int ks = 0; ks < 4; ks++) {
            uint32_t afh[2][4], afl[2][4];
            const int chA = 2 * ks + aChG;
#pragma unroll
            for (int mt = 0; mt < 2; mt++) {
                int row = aRow0 + mt * 16;
                uint32_t ao = row * 128 + ((chA ^ (row & 7)) << 4);
                ldsm4(afh[mt], sb + SMA_HI + ao);
                ldsm4(afl[mt], sb + SMA_LO + ao);
            }
            const int chB = 2 * ks + bChG;
#pragma unroll
            for (int p = 0; p < 3; p++) {
                uint32_t bf[4];
                int row = bRow0 + p * 16;
                ldsm4(bf, sb + SMB + row * 128 + ((chB ^ (row & 7)) << 4));
#pragma unroll
                for (int mt = 0; mt < 2; mt++) {
                    mma16816(acc[mt][2 * p],     afh[mt], bf[0], bf[1]);
                    mma16816(acc[mt][2 * p + 1], afh[mt], bf[2], bf[3]);
                    mma16816(acc[mt][2 * p],     afl[mt], bf[0], bf[1]);
                    mma16816(acc[mt][2 * p + 1], afl[mt], bf[2], bf[3]);
                }
            }
        }
        __syncthreads();
    }

#pragma unroll
    for (int mt = 0; mt < 2; mt++) {
#pragma unroll
        for (int nt = 0; nt < 6; nt++) {
            int col = (wid & 3) * 48 + nt * 8 + (lane & 3) * 2;
            float b0 = bias[col];
            float b1 = bias[col + 1];
#pragma unroll
            for (int rh = 0; rh < 2; rh++) {
                int t = (wid >> 2) * 32 + mt * 16 + (lane >> 2) + rh * 8;
                float v0 = acc[mt][nt][2 * rh + 0] + b0;
                float v1 = acc[mt][nt][2 * rh + 1] + b1;
                *reinterpret_cast<float2*>(out + (size_t)(mBase + t) * CDIM + col)
                    = make_float2(v0, v1);
            }
        }
    }
}

// ---------------------------------------------------------------------------
extern "C" void kernel_launch(void* const* d_in, const int* in_sizes, int n_in,
                              void* d_out, int out_size) {
    const float* x      = (const float*)d_in[0];
    const float* mask   = (const float*)d_in[1];
    const float* qkv_w  = (const float*)d_in[2];
    const float* qkv_b  = (const float*)d_in[3];
    const float* proj_w = (const float*)d_in[4];
    const float* proj_b = (const float*)d_in[5];
    const float* table  = (const float*)d_in[6];

    float* out = (float*)d_out;
    float* attn_out = out + OUT0_ELEMS;

    cudaFuncSetAttribute(fused_kernel, cudaFuncAttributeMaxDynamicSharedMemorySize, FUSED_SMEM);
    cudaFuncSetAttribute(proj_gemm, cudaFuncAttributeMaxDynamicSharedMemorySize, GEMM_SMEM);

    // 1) bias gather + weight fp16 conversions
    bias_kernel<<<96, 256>>>(table);
    {
        int w4 = (3 * CDIM * CDIM) / 4;
        convert_kernel<1><<<(w4 + 255) / 256, 256>>>(qkv_w, w4);
        int p4 = (CDIM * CDIM) / 4;
        convert_kernel<2><<<(p4 + 255) / 256, 256>>>(proj_w, p4);
    }

    // 2) fused QKV + attention: writes attn (fp32) + O (fp16 hi/lo)
    fused_kernel<<<NWIN, 256, FUSED_SMEM>>>(x, qkv_b, mask, attn_out);

    // 3) output projection
    proj_gemm<<<dim3(1, NWIN), 256, GEMM_SMEM>>>(proj_b, out);

    (void)in_sizes; (void)n_in; (void)out_size;
}

// round 9
// speedup vs baseline: 1.5027x; 1.0855x over previous
#include <cuda_runtime.h>
#include <cuda_fp16.h>
#include <cstdint>

// Problem constants
#define NWIN   4096
#define NTOK   64
#define CDIM   192
#define NHEAD  6
#define HDIM   32
#define NMASK  64
#define MROWS  (NWIN * NTOK)          // 262144
#define SCALE_Q 0.17677669529663687f

#define OUT0_ELEMS  ((size_t)MROWS * CDIM)
#define ATTN_ELEMS  ((size_t)NWIN * NHEAD * NTOK * NTOK)

// ---------------- device scratch (allocation-free) ----------------
static __device__ float g_bias[NHEAD * NTOK * NTOK];

static __device__ __half g_ohi[MROWS * CDIM];        // attn output, fp16 hi/lo
static __device__ __half g_olo[MROWS * CDIM];
static __device__ __half g_wq[3 * CDIM * CDIM];      // weights, single fp16
static __device__ __half g_wp[CDIM * CDIM];

// ---------------- helpers ----------------
__device__ __forceinline__ uint32_t smem_u32(const void* p) {
    uint32_t a;
    asm("{ .reg .u64 t; cvta.to.shared.u64 t, %1; cvt.u32.u64 %0, t; }" : "=r"(a) : "l"(p));
    return a;
}
__device__ __forceinline__ void ldsm4(uint32_t (&r)[4], uint32_t a) {
    asm volatile("ldmatrix.sync.aligned.m8n8.x4.shared.b16 {%0,%1,%2,%3}, [%4];"
                 : "=r"(r[0]), "=r"(r[1]), "=r"(r[2]), "=r"(r[3]) : "r"(a));
}
__device__ __forceinline__ void ldsm4t(uint32_t (&r)[4], uint32_t a) {
    asm volatile("ldmatrix.sync.aligned.m8n8.x4.trans.shared.b16 {%0,%1,%2,%3}, [%4];"
                 : "=r"(r[0]), "=r"(r[1]), "=r"(r[2]), "=r"(r[3]) : "r"(a));
}
__device__ __forceinline__ void mma16816(float (&d)[4], const uint32_t (&a)[4],
                                         uint32_t b0, uint32_t b1) {
    asm volatile("mma.sync.aligned.m16n8k16.row.col.f32.f16.f16.f32 "
                 "{%0,%1,%2,%3}, {%4,%5,%6,%7}, {%8,%9}, {%0,%1,%2,%3};"
                 : "+f"(d[0]), "+f"(d[1]), "+f"(d[2]), "+f"(d[3])
                 : "r"(a[0]), "r"(a[1]), "r"(a[2]), "r"(a[3]), "r"(b0), "r"(b1));
}
__device__ __forceinline__ uint32_t packh(float a, float b) {
    __half2 t = __floats2half2_rn(a, b);
    return *reinterpret_cast<uint32_t*>(&t);
}
__device__ __forceinline__ void split2h(float a, float b, uint32_t& hi, uint32_t& lo) {
    __half ha = __float2half_rn(a), hb = __float2half_rn(b);
    float ra = a - __half2float(ha);
    float rb = b - __half2float(hb);
    __half2 th = __halves2half2(ha, hb);
    hi = *reinterpret_cast<uint32_t*>(&th);
    lo = packh(ra, rb);
}
__device__ __forceinline__ void cpasync16(uint32_t dst, const void* src) {
    asm volatile("cp.async.cg.shared.global [%0], [%1], 16;" :: "r"(dst), "l"(src));
}

// ---------------- bias gather ----------------
__global__ void bias_kernel(const float* __restrict__ table) {
    int e = blockIdx.x * 256 + threadIdx.x;
    int h  = e >> 12;
    int nm = e & 4095;
    int n = nm >> 6, m = nm & 63;
    int idx = ((n >> 3) - (m >> 3) + 7) * 15 + ((n & 7) - (m & 7) + 7);
    g_bias[e] = table[idx * NHEAD + h];
}

// ---------------- fp32 -> single fp16 (weights) ----------------
template<int DST>   // 1 = qkv_w, 2 = proj_w
__global__ void __launch_bounds__(256)
convert_kernel(const float* __restrict__ src, int n4) {
    int i = blockIdx.x * 256 + threadIdx.x;
    if (i >= n4) return;
    __half* dst = (DST == 1) ? g_wq : g_wp;
    float4 v = reinterpret_cast<const float4*>(src)[i];
    reinterpret_cast<uint2*>(dst)[i] =
        make_uint2(packh(v.x, v.y), packh(v.z, v.w));
}

// ================== FUSED QKV + ATTENTION (256 threads) ==================
// Smem map (bytes):
//  [0, 49152)         A hi/lo (64x192 fp16 x2) -> hi region reused for V (single)
//  [49152, 122880)    B ring: 3 x 24576, 192x64 fp16 (single), 128B rows
//  [122880, 172032)   Q hi/lo (per-head layout: 4096 B per head per part)
//  [172032, 196608)   K (single, per-head layout)
#define FA_HI 0
#define FA_LO 24576
#define FB    49152
#define FB_ST 24576
#define FQ_HI 122880
#define FQ_LO 147456
#define FK    172032
#define FV    0
#define FUSED_SMEM 196608

// load W chunk (s, kk64): 192 rows x 64 fp16, 128B swizzled rows
__device__ __forceinline__ void issueB64(uint32_t sb, int tid, int s, int kk, int buf) {
    uint32_t dstb = sb + FB + buf * FB_ST;
#pragma unroll
    for (int i = 0; i < 6; i++) {
        int idx = tid + i * 256;          // 0..1535
        int row = idx >> 3, ch = idx & 7;
        size_t src = (size_t)(s * CDIM + row) * CDIM + kk * 64 + ch * 8;
        cpasync16(dstb + row * 128 + ((ch ^ (row & 7)) << 4), g_wq + src);
    }
    asm volatile("cp.async.commit_group;" ::: "memory");
}

__global__ void __launch_bounds__(256, 1)
fused_kernel(const float* __restrict__ X, const float* __restrict__ qkv_b,
             const float* __restrict__ mask, float* __restrict__ attn_out) {
    extern __shared__ char sm[];
    const uint32_t sb = smem_u32(sm);
    const int tid = threadIdx.x;
    const int wid = tid >> 5, lane = tid & 31;
    const int b = blockIdx.x;
    const int mBase = b * 64;
    const int g = lane >> 3, rl = lane & 7;

    // prefetch W chunks 0,1 (ring of 3)
    issueB64(sb, tid, 0, 0, 0);
    issueB64(sb, tid, 0, 1, 1);

    // load A: 64 rows x 192 fp32 -> fp16 hi/lo, swizzled (3 subtiles of 64 cols)
#pragma unroll
    for (int i = 0; i < 6; i++) {
        int idx = tid + i * 256;          // 0..1535
        int row = idx / 24, cc = idx % 24;
        const float* srcp = X + (size_t)(mBase + row) * CDIM + cc * 8;
        float4 f0 = *reinterpret_cast<const float4*>(srcp);
        float4 f1 = *reinterpret_cast<const float4*>(srcp + 4);
        uint32_t h0, h1, h2, h3, l0, l1, l2, l3;
        split2h(f0.x, f0.y, h0, l0);
        split2h(f0.z, f0.w, h1, l1);
        split2h(f1.x, f1.y, h2, l2);
        split2h(f1.z, f1.w, h3, l3);
        int sub = cc >> 3, ch = cc & 7;
        uint32_t d = row * 384 + sub * 128 + ((ch ^ (row & 7)) << 4);
        *reinterpret_cast<uint4*>(sm + FA_HI + d) = make_uint4(h0, h1, h2, h3);
        *reinterpret_cast<uint4*>(sm + FA_LO + d) = make_uint4(l0, l1, l2, l3);
    }

    // Phase-1 warp mapping: 8 warps, warp tile 32(M) x 48(N)
    const int aRow0 = (wid >> 2) * 32 + ((g & 1) << 3) + rl;
    const int aChG  = g >> 1;
    const int bRow0 = (wid & 3) * 48 + ((g >> 1) << 3) + rl;
    const int bChG  = g & 1;

    float acc[2][6][4];

    // ---------------- Phase 1: QKV GEMM, 9 K64-chunks pipelined ----------------
    for (int cur = 0; cur < 9; cur++) {
        const int s = cur / 3, kk = cur % 3;
        if (kk == 0) {
#pragma unroll
            for (int a = 0; a < 2; a++)
#pragma unroll
                for (int b2 = 0; b2 < 6; b2++)
#pragma unroll
                    for (int c = 0; c < 4; c++) acc[a][b2][c] = 0.0f;
        }
        if (cur < 8) { asm volatile("cp.async.wait_group 1;" ::: "memory"); }
        else         { asm volatile("cp.async.wait_group 0;" ::: "memory"); }
        __syncthreads();
        if (cur + 2 < 9) {
            int nxt = cur + 2;
            issueB64(sb, tid, nxt / 3, nxt % 3, nxt % 3);
        }
        const uint32_t bufb = sb + FB + (cur % 3) * FB_ST;
        const uint32_t aHIb = sb + FA_HI + kk * 128;
        const uint32_t aLOb = sb + FA_LO + kk * 128;

#pragma unroll
        for (int ks = 0; ks < 4; ks++) {
            uint32_t afh[2][4], afl[2][4], bf[3][4];
            const int chA = 2 * ks + aChG;
#pragma unroll
            for (int mt = 0; mt < 2; mt++) {
                int row = aRow0 + mt * 16;
                uint32_t ao = row * 384 + ((chA ^ (row & 7)) << 4);
                ldsm4(afh[mt], aHIb + ao);
                ldsm4(afl[mt], aLOb + ao);
            }
            const int chB = 2 * ks + bChG;
#pragma unroll
            for (int p = 0; p < 3; p++) {
                int row = bRow0 + p * 16;
                ldsm4(bf[p], bufb + row * 128 + ((chB ^ (row & 7)) << 4));
            }
            // all-hi block, then all-lo block: acc RAW gap >= 12 MMAs
#pragma unroll
            for (int p = 0; p < 3; p++)
#pragma unroll
                for (int mt = 0; mt < 2; mt++) {
                    mma16816(acc[mt][2 * p],     afh[mt], bf[p][0], bf[p][1]);
                    mma16816(acc[mt][2 * p + 1], afh[mt], bf[p][2], bf[p][3]);
                }
#pragma unroll
            for (int p = 0; p < 3; p++)
#pragma unroll
                for (int mt = 0; mt < 2; mt++) {
                    mma16816(acc[mt][2 * p],     afl[mt], bf[p][0], bf[p][1]);
                    mma16816(acc[mt][2 * p + 1], afl[mt], bf[p][2], bf[p][3]);
                }
        }

        if (kk == 2) {
            // epilogue: write this s's 64x192 into smem per-head layout
            if (s == 2) __syncthreads();    // all warps done reading A before V overwrite
            const float sc = (s == 0) ? SCALE_Q : 1.0f;
#pragma unroll
            for (int mt = 0; mt < 2; mt++) {
#pragma unroll
                for (int nt = 0; nt < 6; nt++) {
                    int col = (wid & 3) * 48 + nt * 8 + (lane & 3) * 2;
                    float b0 = qkv_b[s * CDIM + col];
                    float b1 = qkv_b[s * CDIM + col + 1];
                    int hh = col >> 5, d = col & 31;
#pragma unroll
                    for (int rh = 0; rh < 2; rh++) {
                        int t = (wid >> 2) * 32 + mt * 16 + (lane >> 2) + rh * 8;
                        float v0 = (acc[mt][nt][2 * rh + 0] + b0) * sc;
                        float v1 = (acc[mt][nt][2 * rh + 1] + b1) * sc;
                        uint32_t off = hh * 4096 + t * 64 +
                                       (((d >> 3) ^ ((t >> 1) & 3)) << 4) + (d & 7) * 2;
                        if (s == 0) {
                            uint32_t hi, lo;
                            split2h(v0, v1, hi, lo);
                            *reinterpret_cast<uint32_t*>(sm + FQ_HI + off) = hi;
                            *reinterpret_cast<uint32_t*>(sm + FQ_LO + off) = lo;
                        } else {
                            uint32_t hv = packh(v0, v1);
                            *reinterpret_cast<uint32_t*>(sm + (s == 1 ? FK : FV) + off) = hv;
                        }
                    }
                }
            }
        }
    }
    __syncthreads();

    // ---------------- Phase 2: attention, 2 teams x 3 iterations = 6 heads -----
    const int team = wid >> 2;           // 0..1
    const int wrow = wid & 3;
    const int r0 = wrow * 16 + (lane >> 2);
    const int q2 = (lane & 3) * 2;
    const float* mp = mask + ((size_t)(b & (NMASK - 1)) << 12);

#pragma unroll
    for (int it = 0; it < 3; it++) {
        const int h = 2 * it + team;
        const uint32_t qoff = h * 4096;

        // hoisted bias + mask loads (overlap the QK^T MMAs below)
        const float* bp = g_bias + ((size_t)h << 12);
        float bm[8][4];
#pragma unroll
        for (int t = 0; t < 8; t++) {
            int cc = 8 * t + q2;
            float2 b0 = *reinterpret_cast<const float2*>(bp + r0 * 64 + cc);
            float2 b1 = *reinterpret_cast<const float2*>(bp + (r0 + 8) * 64 + cc);
            float2 m0 = *reinterpret_cast<const float2*>(mp + r0 * 64 + cc);
            float2 m1 = *reinterpret_cast<const float2*>(mp + (r0 + 8) * 64 + cc);
            bm[t][0] = b0.x + m0.x; bm[t][1] = b0.y + m0.y;
            bm[t][2] = b1.x + m1.x; bm[t][3] = b1.y + m1.y;
        }

        // S = Q K^T: 2 passes (Q hi/lo x K single)
        float S[8][4];
#pragma unroll
        for (int t = 0; t < 8; t++)
#pragma unroll
            for (int j = 0; j < 4; j++) S[t][j] = 0.0f;

#pragma unroll
        for (int pass = 0; pass < 2; pass++) {
            const uint32_t qb = sb + (pass ? FQ_LO : FQ_HI) + qoff;
            const uint32_t kb = sb + FK + qoff;
#pragma unroll
            for (int ks = 0; ks < 2; ks++) {
                uint32_t af[4];
                {
                    int row = wrow * 16 + ((g & 1) << 3) + rl;
                    int c = (2 * ks + (g >> 1)) ^ ((row >> 1) & 3);
                    ldsm4(af, qb + row * 64 + (c << 4));
                }
#pragma unroll
                for (int nt2 = 0; nt2 < 4; nt2++) {
                    uint32_t bf[4];
                    {
                        int row = nt2 * 16 + ((g >> 1) << 3) + rl;
                        int c = (2 * ks + (g & 1)) ^ ((row >> 1) & 3);
                        ldsm4(bf, kb + row * 64 + (c << 4));
                    }
                    mma16816(S[2 * nt2],     af, bf[0], bf[1]);
                    mma16816(S[2 * nt2 + 1], af, bf[2], bf[3]);
                }
            }
        }

        // bias + mask + softmax on fragments
        float mlo = -1e30f, mhi = -1e30f;
#pragma unroll
        for (int t = 0; t < 8; t++) {
            S[t][0] += bm[t][0]; S[t][1] += bm[t][1];
            S[t][2] += bm[t][2]; S[t][3] += bm[t][3];
            mlo = fmaxf(mlo, fmaxf(S[t][0], S[t][1]));
            mhi = fmaxf(mhi, fmaxf(S[t][2], S[t][3]));
        }
#pragma unroll
        for (int off = 1; off < 4; off <<= 1) {
            mlo = fmaxf(mlo, __shfl_xor_sync(0xffffffffu, mlo, off));
            mhi = fmaxf(mhi, __shfl_xor_sync(0xffffffffu, mhi, off));
        }
        float slo = 0.0f, shi = 0.0f;
#pragma unroll
        for (int t = 0; t < 8; t++) {
            S[t][0] = __expf(S[t][0] - mlo); S[t][1] = __expf(S[t][1] - mlo);
            S[t][2] = __expf(S[t][2] - mhi); S[t][3] = __expf(S[t][3] - mhi);
            slo += S[t][0] + S[t][1];
            shi += S[t][2] + S[t][3];
        }
#pragma unroll
        for (int off = 1; off < 4; off <<= 1) {
            slo += __shfl_xor_sync(0xffffffffu, slo, off);
            shi += __shfl_xor_sync(0xffffffffu, shi, off);
        }
        const float ilo = 1.0f / slo, ihi = 1.0f / shi;

        // normalize, write attn, build P fragments (fp16 hi/lo)
        const size_t ab = ((size_t)b * NHEAD + h) << 12;
        uint32_t Ph[4][4], Pl[4][4];
#pragma unroll
        for (int t = 0; t < 8; t++) {
            S[t][0] *= ilo; S[t][1] *= ilo;
            S[t][2] *= ihi; S[t][3] *= ihi;
            *reinterpret_cast<float2*>(attn_out + ab + (size_t)r0 * 64 + 8 * t + q2)
                = make_float2(S[t][0], S[t][1]);
            *reinterpret_cast<float2*>(attn_out + ab + (size_t)(r0 + 8) * 64 + 8 * t + q2)
                = make_float2(S[t][2], S[t][3]);
        }
#pragma unroll
        for (int kt = 0; kt < 4; kt++) {
            split2h(S[2 * kt][0],     S[2 * kt][1],     Ph[kt][0], Pl[kt][0]);
            split2h(S[2 * kt][2],     S[2 * kt][3],     Ph[kt][1], Pl[kt][1]);
            split2h(S[2 * kt + 1][0], S[2 * kt + 1][1], Ph[kt][2], Pl[kt][2]);
            split2h(S[2 * kt + 1][2], S[2 * kt + 1][3], Ph[kt][3], Pl[kt][3]);
        }

        // O = P V: 2 passes, reordered so same-O RAW gap >= 4 MMAs
        float O[4][4];
#pragma unroll
        for (int t = 0; t < 4; t++)
#pragma unroll
            for (int j = 0; j < 4; j++) O[t][j] = 0.0f;

        const uint32_t vb = sb + FV + qoff;
#pragma unroll
        for (int kt = 0; kt < 4; kt++) {
            uint32_t bf0[4], bf1[4];
            int row = kt * 16 + ((g & 1) << 3) + rl;
            int c0 = (0 + (g >> 1)) ^ ((row >> 1) & 3);
            int c1 = (2 + (g >> 1)) ^ ((row >> 1) & 3);
            ldsm4t(bf0, vb + row * 64 + (c0 << 4));
            ldsm4t(bf1, vb + row * 64 + (c1 << 4));
            mma16816(O[0], Ph[kt], bf0[0], bf0[1]);
            mma16816(O[1], Ph[kt], bf0[2], bf0[3]);
            mma16816(O[2], Ph[kt], bf1[0], bf1[1]);
            mma16816(O[3], Ph[kt], bf1[2], bf1[3]);
            mma16816(O[0], Pl[kt], bf0[0], bf0[1]);
            mma16816(O[1], Pl[kt], bf0[2], bf0[3]);
            mma16816(O[2], Pl[kt], bf1[0], bf1[1]);
            mma16816(O[3], Pl[kt], bf1[2], bf1[3]);
        }

        // write O as fp16 hi/lo, layout [b][tok][h*32+d]
        const size_t ob = (size_t)b * NTOK * CDIM + h * HDIM;
#pragma unroll
        for (int dt = 0; dt < 4; dt++) {
            int col = 8 * dt + q2;
            uint32_t hi0, lo0, hi1, lo1;
            split2h(O[dt][0], O[dt][1], hi0, lo0);
            split2h(O[dt][2], O[dt][3], hi1, lo1);
            *reinterpret_cast<uint32_t*>(g_ohi + ob + (size_t)r0 * CDIM + col)       = hi0;
            *reinterpret_cast<uint32_t*>(g_olo + ob + (size_t)r0 * CDIM + col)       = lo0;
            *reinterpret_cast<uint32_t*>(g_ohi + ob + (size_t)(r0 + 8) * CDIM + col) = hi1;
            *reinterpret_cast<uint32_t*>(g_olo + ob + (size_t)(r0 + 8) * CDIM + col) = lo1;
        }
    }
}

// ---------------- proj GEMM: O (fp16 hi/lo) x Wp (fp16 single) ----------------
#define SMA_HI 0
#define SMA_LO 8192
#define SMB    16384
#define GEMM_SMEM 40960

__global__ void __launch_bounds__(256, 3)
proj_gemm(const float* __restrict__ bias, float* __restrict__ out) {
    extern __shared__ char sm[];
    const int tid = threadIdx.x;
    const int wid = tid >> 5, lane = tid & 31;
    const int mBase = blockIdx.y * 64;

    const uint32_t sb = smem_u32(sm);

    float acc[2][6][4];
#pragma unroll
    for (int a = 0; a < 2; a++)
#pragma unroll
        for (int b = 0; b < 6; b++)
#pragma unroll
            for (int c = 0; c < 4; c++) acc[a][b][c] = 0.0f;

    const int g  = lane >> 3, rl = lane & 7;
    const int aRow0 = (wid >> 2) * 32 + ((g & 1) << 3) + rl;
    const int aChG  = g >> 1;
    const int bRow0 = (wid & 3) * 48 + ((g >> 1) << 3) + rl;
    const int bChG  = g & 1;

    for (int kc = 0; kc < 3; kc++) {
        // A: 64 rows x 64 fp16 (hi+lo)
#pragma unroll
        for (int i = 0; i < 2; i++) {
            int idx = tid + i * 256;      // 0..511
            int row = idx >> 3, ch = idx & 7;
            size_t src = (size_t)(mBase + row) * CDIM + kc * 64 + ch * 8;
            uint32_t dst = row * 128 + ((ch ^ (row & 7)) << 4);
            *reinterpret_cast<uint4*>(sm + SMA_HI + dst) =
                *reinterpret_cast<const uint4*>(g_ohi + src);
            *reinterpret_cast<uint4*>(sm + SMA_LO + dst) =
                *reinterpret_cast<const uint4*>(g_olo + src);
        }
        // B: 192 rows x 64 fp16 (single)
#pragma unroll
        for (int i = 0; i < 6; i++) {
            int idx = tid + i * 256;      // 0..1535
            int row = idx >> 3, ch = idx & 7;
            size_t src = (size_t)row * CDIM + kc * 64 + ch * 8;
            uint32_t dst = row * 128 + ((ch ^ (row & 7)) << 4);
            *reinterpret_cast<uint4*>(sm + SMB + dst) =
                *reinterpret_cast<const uint4*>(g_wp + src);
        }
        __syncthreads();

#pragma unroll
        for (int ks = 0; ks < 4; ks++) {
            uint32_t afh[2][4], afl[2][4], bf[3][4];
            const int chA = 2 * ks + aChG;
#pragma unroll
            for (int mt = 0; mt < 2; mt++) {
                int row = aRow0 + mt * 16;
                uint32_t ao = row * 128 + ((chA ^ (row & 7)) << 4);
                ldsm4(afh[mt], sb + SMA_HI + ao);
                ldsm4(afl[mt], sb + SMA_LO + ao);
            }
            const int chB = 2 * ks + bChG;
#pragma unroll
            for (int p = 0; p < 3; p++) {
                int row = bRow0 + p * 16;
                ldsm4(bf[p], sb + SMB + row * 128 + ((chB ^ (row & 7)) << 4));
            }
#pragma unroll
            for (int p = 0; p < 3; p++)
#pragma unroll
                for (int mt = 0; mt < 2; mt++) {
                    mma16816(acc[mt][2 * p],     afh[mt], bf[p][0], bf[p][1]);
                    mma16816(acc[mt][2 * p + 1], afh[mt], bf[p][2], bf[p][3]);
                }
#pragma unroll
            for (int p = 0; p < 3; p++)
#pragma unroll
                for (int mt = 0; mt < 2; mt++) {
                    mma16816(acc[mt][2 * p],     afl[mt], bf[p][0], bf[p][1]);
                    mma16816(acc[mt][2 * p + 1], afl[mt], bf[p][2], bf[p][3]);
                }
        }
        __syncthreads();
    }

#pragma unroll
    for (int mt = 0; mt < 2; mt++) {
#pragma unroll
        for (int nt = 0; nt < 6; nt++) {
            int col = (wid & 3) * 48 + nt * 8 + (lane & 3) * 2;
            float b0 = bias[col];
            float b1 = bias[col + 1];
#pragma unroll
            for (int rh = 0; rh < 2; rh++) {
                int t = (wid >> 2) * 32 + mt * 16 + (lane >> 2) + rh * 8;
                float v0 = acc[mt][nt][2 * rh + 0] + b0;
                float v1 = acc[mt][nt][2 * rh + 1] + b1;
                *reinterpret_cast<float2*>(out + (size_t)(mBase + t) * CDIM + col)
                    = make_float2(v0, v1);
            }
        }
    }
}

// ---------------------------------------------------------------------------
extern "C" void kernel_launch(void* const* d_in, const int* in_sizes, int n_in,
                              void* d_out, int out_size) {
    const float* x      = (const float*)d_in[0];
    const float* mask   = (const float*)d_in[1];
    const float* qkv_w  = (const float*)d_in[2];
    const float* qkv_b  = (const float*)d_in[3];
    const float* proj_w = (const float*)d_in[4];
    const float* proj_b = (const float*)d_in[5];
    const float* table  = (const float*)d_in[6];

    float* out = (float*)d_out;
    float* attn_out = out + OUT0_ELEMS;

    cudaFuncSetAttribute(fused_kernel, cudaFuncAttributeMaxDynamicSharedMemorySize, FUSED_SMEM);
    cudaFuncSetAttribute(proj_gemm, cudaFuncAttributeMaxDynamicSharedMemorySize, GEMM_SMEM);

    // 1) bias gather + weight fp16 conversions
    bias_kernel<<<96, 256>>>(table);
    {
        int w4 = (3 * CDIM * CDIM) / 4;
        convert_kernel<1><<<(w4 + 255) / 256, 256>>>(qkv_w, w4);
        int p4 = (CDIM * CDIM) / 4;
        convert_kernel<2><<<(p4 + 255) / 256, 256>>>(proj_w, p4);
    }

    // 2) fused QKV + attention: writes attn (fp32) + O (fp16 hi/lo)
    fused_kernel<<<NWIN, 256, FUSED_SMEM>>>(x, qkv_b, mask, attn_out);

    // 3) output projection
    proj_gemm<<<dim3(1, NWIN), 256, GEMM_SMEM>>>(proj_b, out);

    (void)in_sizes; (void)n_in; (void)out_size;
}

// round 10
// speedup vs baseline: 1.5030x; 1.0002x over previous
#include <cuda_runtime.h>
#include <cuda_fp16.h>
#include <cstdint>

// Problem constants
#define NWIN   4096
#define NTOK   64
#define CDIM   192
#define NHEAD  6
#define HDIM   32
#define NMASK  64
#define MROWS  (NWIN * NTOK)          // 262144
#define SCALE_Q 0.17677669529663687f

#define OUT0_ELEMS  ((size_t)MROWS * CDIM)
#define ATTN_ELEMS  ((size_t)NWIN * NHEAD * NTOK * NTOK)

// ---------------- device scratch (allocation-free) ----------------
static __device__ float g_bias[NHEAD * NTOK * NTOK];

static __device__ __half g_ohi[MROWS * CDIM];        // attn output, fp16 hi/lo
static __device__ __half g_olo[MROWS * CDIM];
static __device__ __half g_wq[3 * CDIM * CDIM];      // weights, single fp16
static __device__ __half g_wp[CDIM * CDIM];

// ---------------- helpers ----------------
__device__ __forceinline__ uint32_t smem_u32(const void* p) {
    uint32_t a;
    asm("{ .reg .u64 t; cvta.to.shared.u64 t, %1; cvt.u32.u64 %0, t; }" : "=r"(a) : "l"(p));
    return a;
}
__device__ __forceinline__ void ldsm4(uint32_t (&r)[4], uint32_t a) {
    asm volatile("ldmatrix.sync.aligned.m8n8.x4.shared.b16 {%0,%1,%2,%3}, [%4];"
                 : "=r"(r[0]), "=r"(r[1]), "=r"(r[2]), "=r"(r[3]) : "r"(a));
}
__device__ __forceinline__ void ldsm4t(uint32_t (&r)[4], uint32_t a) {
    asm volatile("ldmatrix.sync.aligned.m8n8.x4.trans.shared.b16 {%0,%1,%2,%3}, [%4];"
                 : "=r"(r[0]), "=r"(r[1]), "=r"(r[2]), "=r"(r[3]) : "r"(a));
}
__device__ __forceinline__ void mma16816(float (&d)[4], const uint32_t (&a)[4],
                                         uint32_t b0, uint32_t b1) {
    asm volatile("mma.sync.aligned.m16n8k16.row.col.f32.f16.f16.f32 "
                 "{%0,%1,%2,%3}, {%4,%5,%6,%7}, {%8,%9}, {%0,%1,%2,%3};"
                 : "+f"(d[0]), "+f"(d[1]), "+f"(d[2]), "+f"(d[3])
                 : "r"(a[0]), "r"(a[1]), "r"(a[2]), "r"(a[3]), "r"(b0), "r"(b1));
}
__device__ __forceinline__ uint32_t packh(float a, float b) {
    __half2 t = __floats2half2_rn(a, b);
    return *reinterpret_cast<uint32_t*>(&t);
}
__device__ __forceinline__ void split2h(float a, float b, uint32_t& hi, uint32_t& lo) {
    __half ha = __float2half_rn(a), hb = __float2half_rn(b);
    float ra = a - __half2float(ha);
    float rb = b - __half2float(hb);
    __half2 th = __halves2half2(ha, hb);
    hi = *reinterpret_cast<uint32_t*>(&th);
    lo = packh(ra, rb);
}
__device__ __forceinline__ void cpasync16(uint32_t dst, const void* src) {
    asm volatile("cp.async.cg.shared.global [%0], [%1], 16;" :: "r"(dst), "l"(src));
}

// ---------------- bias gather ----------------
__global__ void bias_kernel(const float* __restrict__ table) {
    int e = blockIdx.x * 256 + threadIdx.x;
    int h  = e >> 12;
    int nm = e & 4095;
    int n = nm >> 6, m = nm & 63;
    int idx = ((n >> 3) - (m >> 3) + 7) * 15 + ((n & 7) - (m & 7) + 7);
    g_bias[e] = table[idx * NHEAD + h];
}

// ---------------- fp32 -> single fp16 (weights) ----------------
template<int DST>
__global__ void __launch_bounds__(256)
convert_kernel(const float* __restrict__ src, int n4) {
    int i = blockIdx.x * 256 + threadIdx.x;
    if (i >= n4) return;
    __half* dst = (DST == 1) ? g_wq : g_wp;
    float4 v = reinterpret_cast<const float4*>(src)[i];
    reinterpret_cast<uint2*>(dst)[i] =
        make_uint2(packh(v.x, v.y), packh(v.z, v.w));
}

// ================== FUSED QKV + ATTENTION (256 threads) ==================
#define FA_HI 0
#define FA_LO 24576
#define FB    49152
#define FB_ST 24576
#define FQ_HI 122880
#define FQ_LO 147456
#define FK    172032
#define FV    0
#define FUSED_SMEM 196608

__device__ __forceinline__ void issueB64(uint32_t sb, int tid, int s, int kk, int buf) {
    uint32_t dstb = sb + FB + buf * FB_ST;
#pragma unroll
    for (int i = 0; i < 6; i++) {
        int idx = tid + i * 256;
        int row = idx >> 3, ch = idx & 7;
        size_t src = (size_t)(s * CDIM + row) * CDIM + kk * 64 + ch * 8;
        cpasync16(dstb + row * 128 + ((ch ^ (row & 7)) << 4), g_wq + src);
    }
    asm volatile("cp.async.commit_group;" ::: "memory");
}

__global__ void __launch_bounds__(256, 1)
fused_kernel(const float* __restrict__ X, const float* __restrict__ qkv_b,
             const float* __restrict__ mask, float* __restrict__ attn_out) {
    extern __shared__ char sm[];
    const uint32_t sb = smem_u32(sm);
    const int tid = threadIdx.x;
    const int wid = tid >> 5, lane = tid & 31;
    const int b = blockIdx.x;
    const int mBase = b * 64;
    const int g = lane >> 3, rl = lane & 7;

    issueB64(sb, tid, 0, 0, 0);
    issueB64(sb, tid, 0, 1, 1);

    // load A: 64 rows x 192 fp32 -> fp16 hi/lo, swizzled
#pragma unroll
    for (int i = 0; i < 6; i++) {
        int idx = tid + i * 256;
        int row = idx / 24, cc = idx % 24;
        const float* srcp = X + (size_t)(mBase + row) * CDIM + cc * 8;
        float4 f0 = *reinterpret_cast<const float4*>(srcp);
        float4 f1 = *reinterpret_cast<const float4*>(srcp + 4);
        uint32_t h0, h1, h2, h3, l0, l1, l2, l3;
        split2h(f0.x, f0.y, h0, l0);
        split2h(f0.z, f0.w, h1, l1);
        split2h(f1.x, f1.y, h2, l2);
        split2h(f1.z, f1.w, h3, l3);
        int sub = cc >> 3, ch = cc & 7;
        uint32_t d = row * 384 + sub * 128 + ((ch ^ (row & 7)) << 4);
        *reinterpret_cast<uint4*>(sm + FA_HI + d) = make_uint4(h0, h1, h2, h3);
        *reinterpret_cast<uint4*>(sm + FA_LO + d) = make_uint4(l0, l1, l2, l3);
    }

    const int aRow0 = (wid >> 2) * 32 + ((g & 1) << 3) + rl;
    const int aChG  = g >> 1;
    const int bRow0 = (wid & 3) * 48 + ((g >> 1) << 3) + rl;
    const int bChG  = g & 1;

    float acc[2][6][4];

    // ---------------- Phase 1: QKV GEMM, 9 K64-chunks, frag double-buffer -----
    for (int cur = 0; cur < 9; cur++) {
        const int s = cur / 3, kk = cur % 3;
        if (kk == 0) {
#pragma unroll
            for (int a = 0; a < 2; a++)
#pragma unroll
                for (int b2 = 0; b2 < 6; b2++)
#pragma unroll
                    for (int c = 0; c < 4; c++) acc[a][b2][c] = 0.0f;
        }
        if (cur < 8) { asm volatile("cp.async.wait_group 1;" ::: "memory"); }
        else         { asm volatile("cp.async.wait_group 0;" ::: "memory"); }
        __syncthreads();
        if (cur + 2 < 9) {
            int nxt = cur + 2;
            issueB64(sb, tid, nxt / 3, nxt % 3, nxt % 3);
        }
        const uint32_t bufb = sb + FB + (cur % 3) * FB_ST;
        const uint32_t aHIb = sb + FA_HI + kk * 128;
        const uint32_t aLOb = sb + FA_LO + kk * 128;

        // fragment double buffer (one k-step lookahead)
        uint32_t afh[2][2][4], afl[2][2][4], bfr[2][3][4];
#define LOAD_FRAGS(KS, BI) do { \
            const int chA = 2 * (KS) + aChG; \
            _Pragma("unroll") \
            for (int mt = 0; mt < 2; mt++) { \
                int row = aRow0 + mt * 16; \
                uint32_t ao = row * 384 + ((chA ^ (row & 7)) << 4); \
                ldsm4(afh[BI][mt], aHIb + ao); \
                ldsm4(afl[BI][mt], aLOb + ao); \
            } \
            const int chB = 2 * (KS) + bChG; \
            _Pragma("unroll") \
            for (int p = 0; p < 3; p++) { \
                int row = bRow0 + p * 16; \
                ldsm4(bfr[BI][p], bufb + row * 128 + ((chB ^ (row & 7)) << 4)); \
            } \
        } while (0)

        LOAD_FRAGS(0, 0);
#pragma unroll
        for (int ks = 0; ks < 4; ks++) {
            const int bi = ks & 1;
            if (ks < 3) LOAD_FRAGS(ks + 1, (ks + 1) & 1);
#pragma unroll
            for (int p = 0; p < 3; p++)
#pragma unroll
                for (int mt = 0; mt < 2; mt++) {
                    mma16816(acc[mt][2 * p],     afh[bi][mt], bfr[bi][p][0], bfr[bi][p][1]);
                    mma16816(acc[mt][2 * p + 1], afh[bi][mt], bfr[bi][p][2], bfr[bi][p][3]);
                }
#pragma unroll
            for (int p = 0; p < 3; p++)
#pragma unroll
                for (int mt = 0; mt < 2; mt++) {
                    mma16816(acc[mt][2 * p],     afl[bi][mt], bfr[bi][p][0], bfr[bi][p][1]);
                    mma16816(acc[mt][2 * p + 1], afl[bi][mt], bfr[bi][p][2], bfr[bi][p][3]);
                }
        }
#undef LOAD_FRAGS

        if (kk == 2) {
            if (s == 2) __syncthreads();
            const float sc = (s == 0) ? SCALE_Q : 1.0f;
#pragma unroll
            for (int mt = 0; mt < 2; mt++) {
#pragma unroll
                for (int nt = 0; nt < 6; nt++) {
                    int col = (wid & 3) * 48 + nt * 8 + (lane & 3) * 2;
                    float b0 = qkv_b[s * CDIM + col];
                    float b1 = qkv_b[s * CDIM + col + 1];
                    int hh = col >> 5, d = col & 31;
#pragma unroll
                    for (int rh = 0; rh < 2; rh++) {
                        int t = (wid >> 2) * 32 + mt * 16 + (lane >> 2) + rh * 8;
                        float v0 = (acc[mt][nt][2 * rh + 0] + b0) * sc;
                        float v1 = (acc[mt][nt][2 * rh + 1] + b1) * sc;
                        uint32_t off = hh * 4096 + t * 64 +
                                       (((d >> 3) ^ ((t >> 1) & 3)) << 4) + (d & 7) * 2;
                        if (s == 0) {
                            uint32_t hi, lo;
                            split2h(v0, v1, hi, lo);
                            *reinterpret_cast<uint32_t*>(sm + FQ_HI + off) = hi;
                            *reinterpret_cast<uint32_t*>(sm + FQ_LO + off) = lo;
                        } else {
                            uint32_t hv = packh(v0, v1);
                            *reinterpret_cast<uint32_t*>(sm + (s == 1 ? FK : FV) + off) = hv;
                        }
                    }
                }
            }
        }
    }
    __syncthreads();

    // ---------------- Phase 2: attention, 2 teams x 3 iterations ----------------
    const int team = wid >> 2;
    const int wrow = wid & 3;
    const int r0 = wrow * 16 + (lane >> 2);
    const int q2 = (lane & 3) * 2;
    const float* mp = mask + ((size_t)(b & (NMASK - 1)) << 12);

#pragma unroll
    for (int it = 0; it < 3; it++) {
        const int h = 2 * it + team;
        const uint32_t qoff = h * 4096;
        const float* bp = g_bias + ((size_t)h << 12);

        // init S directly with bias + mask (MMA accumulates on top)
        float S[8][4];
#pragma unroll
        for (int t = 0; t < 8; t++) {
            int cc = 8 * t + q2;
            float2 b0 = *reinterpret_cast<const float2*>(bp + r0 * 64 + cc);
            float2 b1 = *reinterpret_cast<const float2*>(bp + (r0 + 8) * 64 + cc);
            float2 m0 = *reinterpret_cast<const float2*>(mp + r0 * 64 + cc);
            float2 m1 = *reinterpret_cast<const float2*>(mp + (r0 + 8) * 64 + cc);
            S[t][0] = b0.x + m0.x; S[t][1] = b0.y + m0.y;
            S[t][2] = b1.x + m1.x; S[t][3] = b1.y + m1.y;
        }

        // preload K fragments once (shared by both Q passes) and Q hi/lo
        const uint32_t qbh = sb + FQ_HI + qoff;
        const uint32_t qbl = sb + FQ_LO + qoff;
        const uint32_t kb  = sb + FK + qoff;
        uint32_t Kf[2][4][4], Qh[2][4], Ql[2][4];
#pragma unroll
        for (int ks = 0; ks < 2; ks++) {
            int qrow = wrow * 16 + ((g & 1) << 3) + rl;
            int qc = (2 * ks + (g >> 1)) ^ ((qrow >> 1) & 3);
            ldsm4(Qh[ks], qbh + qrow * 64 + (qc << 4));
            ldsm4(Ql[ks], qbl + qrow * 64 + (qc << 4));
#pragma unroll
            for (int nt2 = 0; nt2 < 4; nt2++) {
                int row = nt2 * 16 + ((g >> 1) << 3) + rl;
                int c = (2 * ks + (g & 1)) ^ ((row >> 1) & 3);
                ldsm4(Kf[ks][nt2], kb + row * 64 + (c << 4));
            }
        }
        // dense MMA block: hi pass then lo pass
#pragma unroll
        for (int ks = 0; ks < 2; ks++)
#pragma unroll
            for (int nt2 = 0; nt2 < 4; nt2++) {
                mma16816(S[2 * nt2],     Qh[ks], Kf[ks][nt2][0], Kf[ks][nt2][1]);
                mma16816(S[2 * nt2 + 1], Qh[ks], Kf[ks][nt2][2], Kf[ks][nt2][3]);
            }
#pragma unroll
        for (int ks = 0; ks < 2; ks++)
#pragma unroll
            for (int nt2 = 0; nt2 < 4; nt2++) {
                mma16816(S[2 * nt2],     Ql[ks], Kf[ks][nt2][0], Kf[ks][nt2][1]);
                mma16816(S[2 * nt2 + 1], Ql[ks], Kf[ks][nt2][2], Kf[ks][nt2][3]);
            }

        // softmax on fragments
        float mlo = -1e30f, mhi = -1e30f;
#pragma unroll
        for (int t = 0; t < 8; t++) {
            mlo = fmaxf(mlo, fmaxf(S[t][0], S[t][1]));
            mhi = fmaxf(mhi, fmaxf(S[t][2], S[t][3]));
        }
#pragma unroll
        for (int off = 1; off < 4; off <<= 1) {
            mlo = fmaxf(mlo, __shfl_xor_sync(0xffffffffu, mlo, off));
            mhi = fmaxf(mhi, __shfl_xor_sync(0xffffffffu, mhi, off));
        }
        float slo = 0.0f, shi = 0.0f;
#pragma unroll
        for (int t = 0; t < 8; t++) {
            S[t][0] = __expf(S[t][0] - mlo); S[t][1] = __expf(S[t][1] - mlo);
            S[t][2] = __expf(S[t][2] - mhi); S[t][3] = __expf(S[t][3] - mhi);
            slo += S[t][0] + S[t][1];
            shi += S[t][2] + S[t][3];
        }
#pragma unroll
        for (int off = 1; off < 4; off <<= 1) {
            slo += __shfl_xor_sync(0xffffffffu, slo, off);
            shi += __shfl_xor_sync(0xffffffffu, shi, off);
        }
        const float ilo = 1.0f / slo, ihi = 1.0f / shi;

        // normalize, write attn, build P fragments
        const size_t ab = ((size_t)b * NHEAD + h) << 12;
        uint32_t Ph[4][4], Pl[4][4];
#pragma unroll
        for (int t = 0; t < 8; t++) {
            S[t][0] *= ilo; S[t][1] *= ilo;
            S[t][2] *= ihi; S[t][3] *= ihi;
            *reinterpret_cast<float2*>(attn_out + ab + (size_t)r0 * 64 + 8 * t + q2)
                = make_float2(S[t][0], S[t][1]);
            *reinterpret_cast<float2*>(attn_out + ab + (size_t)(r0 + 8) * 64 + 8 * t + q2)
                = make_float2(S[t][2], S[t][3]);
        }
#pragma unroll
        for (int kt = 0; kt < 4; kt++) {
            split2h(S[2 * kt][0],     S[2 * kt][1],     Ph[kt][0], Pl[kt][0]);
            split2h(S[2 * kt][2],     S[2 * kt][3],     Ph[kt][1], Pl[kt][1]);
            split2h(S[2 * kt + 1][0], S[2 * kt + 1][1], Ph[kt][2], Pl[kt][2]);
            split2h(S[2 * kt + 1][2], S[2 * kt + 1][3], Ph[kt][3], Pl[kt][3]);
        }

        // O = P V: preload all V fragments, then dense MMA
        float O[4][4];
#pragma unroll
        for (int t = 0; t < 4; t++)
#pragma unroll
            for (int j = 0; j < 4; j++) O[t][j] = 0.0f;

        const uint32_t vb = sb + FV + qoff;
        uint32_t Vf[4][2][4];
#pragma unroll
        for (int kt = 0; kt < 4; kt++) {
            int row = kt * 16 + ((g & 1) << 3) + rl;
            int c0 = (0 + (g >> 1)) ^ ((row >> 1) & 3);
            int c1 = (2 + (g >> 1)) ^ ((row >> 1) & 3);
            ldsm4t(Vf[kt][0], vb + row * 64 + (c0 << 4));
            ldsm4t(Vf[kt][1], vb + row * 64 + (c1 << 4));
        }
#pragma unroll
        for (int kt = 0; kt < 4; kt++) {
            mma16816(O[0], Ph[kt], Vf[kt][0][0], Vf[kt][0][1]);
            mma16816(O[1], Ph[kt], Vf[kt][0][2], Vf[kt][0][3]);
            mma16816(O[2], Ph[kt], Vf[kt][1][0], Vf[kt][1][1]);
            mma16816(O[3], Ph[kt], Vf[kt][1][2], Vf[kt][1][3]);
        }
#pragma unroll
        for (int kt = 0; kt < 4; kt++) {
            mma16816(O[0], Pl[kt], Vf[kt][0][0], Vf[kt][0][1]);
            mma16816(O[1], Pl[kt], Vf[kt][0][2], Vf[kt][0][3]);
            mma16816(O[2], Pl[kt], Vf[kt][1][0], Vf[kt][1][1]);
            mma16816(O[3], Pl[kt], Vf[kt][1][2], Vf[kt][1][3]);
        }

        // write O as fp16 hi/lo
        const size_t ob = (size_t)b * NTOK * CDIM + h * HDIM;
#pragma unroll
        for (int dt = 0; dt < 4; dt++) {
            int col = 8 * dt + q2;
            uint32_t hi0, lo0, hi1, lo1;
            split2h(O[dt][0], O[dt][1], hi0, lo0);
            split2h(O[dt][2], O[dt][3], hi1, lo1);
            *reinterpret_cast<uint32_t*>(g_ohi + ob + (size_t)r0 * CDIM + col)       = hi0;
            *reinterpret_cast<uint32_t*>(g_olo + ob + (size_t)r0 * CDIM + col)       = lo0;
            *reinterpret_cast<uint32_t*>(g_ohi + ob + (size_t)(r0 + 8) * CDIM + col) = hi1;
            *reinterpret_cast<uint32_t*>(g_olo + ob + (size_t)(r0 + 8) * CDIM + col) = lo1;
        }
    }
}

// ---------------- proj GEMM: O (fp16 hi/lo) x Wp (fp16 single) ----------------
#define SMA_HI 0
#define SMA_LO 8192
#define SMB    16384
#define GEMM_SMEM 40960

__global__ void __launch_bounds__(256, 3)
proj_gemm(const float* __restrict__ bias, float* __restrict__ out) {
    extern __shared__ char sm[];
    const int tid = threadIdx.x;
    const int wid = tid >> 5, lane = tid & 31;
    const int mBase = blockIdx.y * 64;

    const uint32_t sb = smem_u32(sm);

    float acc[2][6][4];
#pragma unroll
    for (int a = 0; a < 2; a++)
#pragma unroll
        for (int b = 0; b < 6; b++)
#pragma unroll
            for (int c = 0; c < 4; c++) acc[a][b][c] = 0.0f;

    const int g  = lane >> 3, rl = lane & 7;
    const int aRow0 = (wid >> 2) * 32 + ((g & 1) << 3) + rl;
    const int aChG  = g >> 1;
    const int bRow0 = (wid & 3) * 48 + ((g >> 1) << 3) + rl;
    const int bChG  = g & 1;

    for (int kc = 0; kc < 3; kc++) {
#pragma unroll
        for (int i = 0; i < 2; i++) {
            int idx = tid + i * 256;
            int row = idx >> 3, ch = idx & 7;
            size_t src = (size_t)(mBase + row) * CDIM + kc * 64 + ch * 8;
            uint32_t dst = row * 128 + ((ch ^ (row & 7)) << 4);
            *reinterpret_cast<uint4*>(sm + SMA_HI + dst) =
                *reinterpret_cast<const uint4*>(g_ohi + src);
            *reinterpret_cast<uint4*>(sm + SMA_LO + dst) =
                *reinterpret_cast<const uint4*>(g_olo + src);
        }
#pragma unroll
        for (int i = 0; i < 6; i++) {
            int idx = tid + i * 256;
            int row = idx >> 3, ch = idx & 7;
            size_t src = (size_t)row * CDIM + kc * 64 + ch * 8;
            uint32_t dst = row * 128 + ((ch ^ (row & 7)) << 4);
            *reinterpret_cast<uint4*>(sm + SMB + dst) =
                *reinterpret_cast<const uint4*>(g_wp + src);
        }
        __syncthreads();

        // fragment double buffer across k-steps
        uint32_t afh[2][2][4], afl[2][2][4], bfr[2][3][4];
#define PLOAD(KS, BI) do { \
            const int chA = 2 * (KS) + aChG; \
            _Pragma("unroll") \
            for (int mt = 0; mt < 2; mt++) { \
                int row = aRow0 + mt * 16; \
                uint32_t ao = row * 128 + ((chA ^ (row & 7)) << 4); \
                ldsm4(afh[BI][mt], sb + SMA_HI + ao); \
                ldsm4(afl[BI][mt], sb + SMA_LO + ao); \
            } \
            const int chB = 2 * (KS) + bChG; \
            _Pragma("unroll") \
            for (int p = 0; p < 3; p++) { \
                int row = bRow0 + p * 16; \
                ldsm4(bfr[BI][p], sb + SMB + row * 128 + ((chB ^ (row & 7)) << 4)); \
            } \
        } while (0)

        PLOAD(0, 0);
#pragma unroll
        for (int ks = 0; ks < 4; ks++) {
            const int bi = ks & 1;
            if (ks < 3) PLOAD(ks + 1, (ks + 1) & 1);
#pragma unroll
            for (int p = 0; p < 3; p++)
#pragma unroll
                for (int mt = 0; mt < 2; mt++) {
                    mma16816(acc[mt][2 * p],     afh[bi][mt], bfr[bi][p][0], bfr[bi][p][1]);
                    mma16816(acc[mt][2 * p + 1], afh[bi][mt], bfr[bi][p][2], bfr[bi][p][3]);
                }
#pragma unroll
            for (int p = 0; p < 3; p++)
#pragma unroll
                for (int mt = 0; mt < 2; mt++) {
                    mma16816(acc[mt][2 * p],     afl[bi][mt], bfr[bi][p][0], bfr[bi][p][1]);
                    mma16816(acc[mt][2 * p + 1], afl[bi][mt], bfr[bi][p][2], bfr[bi][p][3]);
                }
        }
#undef PLOAD
        __syncthreads();
    }

#pragma unroll
    for (int mt = 0; mt < 2; mt++) {
#pragma unroll
        for (int nt = 0; nt < 6; nt++) {
            int col = (wid & 3) * 48 + nt * 8 + (lane & 3) * 2;
            float b0 = bias[col];
            float b1 = bias[col + 1];
#pragma unroll
            for (int rh = 0; rh < 2; rh++) {
                int t = (wid >> 2) * 32 + mt * 16 + (lane >> 2) + rh * 8;
                float v0 = acc[mt][nt][2 * rh + 0] + b0;
                float v1 = acc[mt][nt][2 * rh + 1] + b1;
                *reinterpret_cast<float2*>(out + (size_t)(mBase + t) * CDIM + col)
                    = make_float2(v0, v1);
            }
        }
    }
}

// ---------------------------------------------------------------------------
extern "C" void kernel_launch(void* const* d_in, const int* in_sizes, int n_in,
                              void* d_out, int out_size) {
    const float* x      = (const float*)d_in[0];
    const float* mask   = (const float*)d_in[1];
    const float* qkv_w  = (const float*)d_in[2];
    const float* qkv_b  = (const float*)d_in[3];
    const float* proj_w = (const float*)d_in[4];
    const float* proj_b = (const float*)d_in[5];
    const float* table  = (const float*)d_in[6];

    float* out = (float*)d_out;
    float* attn_out = out + OUT0_ELEMS;

    cudaFuncSetAttribute(fused_kernel, cudaFuncAttributeMaxDynamicSharedMemorySize, FUSED_SMEM);
    cudaFuncSetAttribute(proj_gemm, cudaFuncAttributeMaxDynamicSharedMemorySize, GEMM_SMEM);

    bias_kernel<<<96, 256>>>(table);
    {
        int w4 = (3 * CDIM * CDIM) / 4;
        convert_kernel<1><<<(w4 + 255) / 256, 256>>>(qkv_w, w4);
        int p4 = (CDIM * CDIM) / 4;
        convert_kernel<2><<<(p4 + 255) / 256, 256>>>(proj_w, p4);
    }

    fused_kernel<<<NWIN, 256, FUSED_SMEM>>>(x, qkv_b, mask, attn_out);
    proj_gemm<<<dim3(1, NWIN), 256, GEMM_SMEM>>>(proj_b, out);

    (void)in_sizes; (void)n_in; (void)out_size;
}

// round 12
// speedup vs baseline: 1.8635x; 1.2399x over previous
#include <cuda_runtime.h>
#include <cuda_fp16.h>
#include <cstdint>

// Problem constants
#define NWIN   4096
#define NTOK   64
#define CDIM   192
#define NHEAD  6
#define HDIM   32
#define NMASK  64
#define MROWS  (NWIN * NTOK)          // 262144
#define SCALE_Q 0.17677669529663687f

#define OUT0_ELEMS  ((size_t)MROWS * CDIM)
#define ATTN_ELEMS  ((size_t)NWIN * NHEAD * NTOK * NTOK)

// ---------------- device scratch (allocation-free) ----------------
static __device__ float g_bias[NHEAD * NTOK * NTOK];

static __device__ __half g_o[MROWS * CDIM];          // attn output, single fp16
static __device__ __half g_wq[3 * CDIM * CDIM];      // weights, single fp16
static __device__ __half g_wp[CDIM * CDIM];

// ---------------- helpers ----------------
__device__ __forceinline__ uint32_t smem_u32(const void* p) {
    uint32_t a;
    asm("{ .reg .u64 t; cvta.to.shared.u64 t, %1; cvt.u32.u64 %0, t; }" : "=r"(a) : "l"(p));
    return a;
}
__device__ __forceinline__ void ldsm4(uint32_t (&r)[4], uint32_t a) {
    asm volatile("ldmatrix.sync.aligned.m8n8.x4.shared.b16 {%0,%1,%2,%3}, [%4];"
                 : "=r"(r[0]), "=r"(r[1]), "=r"(r[2]), "=r"(r[3]) : "r"(a));
}
__device__ __forceinline__ void ldsm4t(uint32_t (&r)[4], uint32_t a) {
    asm volatile("ldmatrix.sync.aligned.m8n8.x4.trans.shared.b16 {%0,%1,%2,%3}, [%4];"
                 : "=r"(r[0]), "=r"(r[1]), "=r"(r[2]), "=r"(r[3]) : "r"(a));
}
__device__ __forceinline__ void mma16816(float (&d)[4], const uint32_t (&a)[4],
                                         uint32_t b0, uint32_t b1) {
    asm volatile("mma.sync.aligned.m16n8k16.row.col.f32.f16.f16.f32 "
                 "{%0,%1,%2,%3}, {%4,%5,%6,%7}, {%8,%9}, {%0,%1,%2,%3};"
                 : "+f"(d[0]), "+f"(d[1]), "+f"(d[2]), "+f"(d[3])
                 : "r"(a[0]), "r"(a[1]), "r"(a[2]), "r"(a[3]), "r"(b0), "r"(b1));
}
__device__ __forceinline__ uint32_t packh(float a, float b) {
    __half2 t = __floats2half2_rn(a, b);
    return *reinterpret_cast<uint32_t*>(&t);
}
__device__ __forceinline__ void split2h(float a, float b, uint32_t& hi, uint32_t& lo) {
    __half ha = __float2half_rn(a), hb = __float2half_rn(b);
    float ra = a - __half2float(ha);
    float rb = b - __half2float(hb);
    __half2 th = __halves2half2(ha, hb);
    hi = *reinterpret_cast<uint32_t*>(&th);
    lo = packh(ra, rb);
}
__device__ __forceinline__ void cpasync16(uint32_t dst, const void* src) {
    asm volatile("cp.async.cg.shared.global [%0], [%1], 16;" :: "r"(dst), "l"(src));
}

// ---------------- bias gather ----------------
__global__ void bias_kernel(const float* __restrict__ table) {
    int e = blockIdx.x * 256 + threadIdx.x;
    int h  = e >> 12;
    int nm = e & 4095;
    int n = nm >> 6, m = nm & 63;
    int idx = ((n >> 3) - (m >> 3) + 7) * 15 + ((n & 7) - (m & 7) + 7);
    g_bias[e] = table[idx * NHEAD + h];
}

// ---------------- fp32 -> single fp16 (weights) ----------------
template<int DST>
__global__ void __launch_bounds__(256)
convert_kernel(const float* __restrict__ src, int n4) {
    int i = blockIdx.x * 256 + threadIdx.x;
    if (i >= n4) return;
    __half* dst = (DST == 1) ? g_wq : g_wp;
    float4 v = reinterpret_cast<const float4*>(src)[i];
    reinterpret_cast<uint2*>(dst)[i] =
        make_uint2(packh(v.x, v.y), packh(v.z, v.w));
}

// ================== FUSED QKV + ATTENTION (256 threads) ==================
#define FA_HI 0
#define FA_LO 24576
#define FB    49152
#define FB_ST 24576
#define FQ_HI 122880
#define FQ_LO 147456
#define FK    172032
#define FV    0
#define FUSED_SMEM 196608

__device__ __forceinline__ void issueB64(uint32_t sb, int tid, int s, int kk, int buf) {
    uint32_t dstb = sb + FB + buf * FB_ST;
#pragma unroll
    for (int i = 0; i < 6; i++) {
        int idx = tid + i * 256;
        int row = idx >> 3, ch = idx & 7;
        size_t src = (size_t)(s * CDIM + row) * CDIM + kk * 64 + ch * 8;
        cpasync16(dstb + row * 128 + ((ch ^ (row & 7)) << 4), g_wq + src);
    }
    asm volatile("cp.async.commit_group;" ::: "memory");
}

__global__ void __launch_bounds__(256, 1)
fused_kernel(const float* __restrict__ X, const float* __restrict__ qkv_b,
             const float* __restrict__ mask, float* __restrict__ attn_out) {
    extern __shared__ char sm[];
    const uint32_t sb = smem_u32(sm);
    const int tid = threadIdx.x;
    const int wid = tid >> 5, lane = tid & 31;
    const int b = blockIdx.x;
    const int mBase = b * 64;
    const int g = lane >> 3, rl = lane & 7;

    issueB64(sb, tid, 0, 0, 0);
    issueB64(sb, tid, 0, 1, 1);

    // load A: 64 rows x 192 fp32 -> fp16 hi/lo, swizzled
#pragma unroll
    for (int i = 0; i < 6; i++) {
        int idx = tid + i * 256;
        int row = idx / 24, cc = idx % 24;
        const float* srcp = X + (size_t)(mBase + row) * CDIM + cc * 8;
        float4 f0 = *reinterpret_cast<const float4*>(srcp);
        float4 f1 = *reinterpret_cast<const float4*>(srcp + 4);
        uint32_t h0, h1, h2, h3, l0, l1, l2, l3;
        split2h(f0.x, f0.y, h0, l0);
        split2h(f0.z, f0.w, h1, l1);
        split2h(f1.x, f1.y, h2, l2);
        split2h(f1.z, f1.w, h3, l3);
        int sub = cc >> 3, ch = cc & 7;
        uint32_t d = row * 384 + sub * 128 + ((ch ^ (row & 7)) << 4);
        *reinterpret_cast<uint4*>(sm + FA_HI + d) = make_uint4(h0, h1, h2, h3);
        *reinterpret_cast<uint4*>(sm + FA_LO + d) = make_uint4(l0, l1, l2, l3);
    }

    const int aRow0 = (wid >> 2) * 32 + ((g & 1) << 3) + rl;
    const int aChG  = g >> 1;
    const int bRow0 = (wid & 3) * 48 + ((g >> 1) << 3) + rl;
    const int bChG  = g & 1;

    float acc[2][6][4];

    // ---------------- Phase 1: QKV GEMM, 9 K64-chunks ----------------
    // s=0 (q): hi+lo A passes (full accuracy); s=1,2 (k,v): hi pass only
    // (k/v are rounded to single fp16 in smem anyway).
    for (int cur = 0; cur < 9; cur++) {
        const int s = cur / 3, kk = cur % 3;
        const bool wantLo = (s == 0);
        if (kk == 0) {
#pragma unroll
            for (int a = 0; a < 2; a++)
#pragma unroll
                for (int b2 = 0; b2 < 6; b2++)
#pragma unroll
                    for (int c = 0; c < 4; c++) acc[a][b2][c] = 0.0f;
        }
        if (cur < 8) { asm volatile("cp.async.wait_group 1;" ::: "memory"); }
        else         { asm volatile("cp.async.wait_group 0;" ::: "memory"); }
        __syncthreads();
        if (cur + 2 < 9) {
            int nxt = cur + 2;
            issueB64(sb, tid, nxt / 3, nxt % 3, nxt % 3);
        }
        const uint32_t bufb = sb + FB + (cur % 3) * FB_ST;
        const uint32_t aHIb = sb + FA_HI + kk * 128;
        const uint32_t aLOb = sb + FA_LO + kk * 128;

#pragma unroll
        for (int ks = 0; ks < 4; ks++) {
            uint32_t afh[2][4], afl[2][4], bf[3][4];
            const int chA = 2 * ks + aChG;
#pragma unroll
            for (int mt = 0; mt < 2; mt++) {
                int row = aRow0 + mt * 16;
                uint32_t ao = row * 384 + ((chA ^ (row & 7)) << 4);
                ldsm4(afh[mt], aHIb + ao);
                if (wantLo) ldsm4(afl[mt], aLOb + ao);
            }
            const int chB = 2 * ks + bChG;
#pragma unroll
            for (int p = 0; p < 3; p++) {
                int row = bRow0 + p * 16;
                ldsm4(bf[p], bufb + row * 128 + ((chB ^ (row & 7)) << 4));
            }
#pragma unroll
            for (int p = 0; p < 3; p++)
#pragma unroll
                for (int mt = 0; mt < 2; mt++) {
                    mma16816(acc[mt][2 * p],     afh[mt], bf[p][0], bf[p][1]);
                    mma16816(acc[mt][2 * p + 1], afh[mt], bf[p][2], bf[p][3]);
                }
            if (wantLo) {
#pragma unroll
                for (int p = 0; p < 3; p++)
#pragma unroll
                    for (int mt = 0; mt < 2; mt++) {
                        mma16816(acc[mt][2 * p],     afl[mt], bf[p][0], bf[p][1]);
                        mma16816(acc[mt][2 * p + 1], afl[mt], bf[p][2], bf[p][3]);
                    }
            }
        }

        if (kk == 2) {
            if (s == 2) __syncthreads();
            const float sc = (s == 0) ? SCALE_Q : 1.0f;
#pragma unroll
            for (int mt = 0; mt < 2; mt++) {
#pragma unroll
                for (int nt = 0; nt < 6; nt++) {
                    int col = (wid & 3) * 48 + nt * 8 + (lane & 3) * 2;
                    float b0 = qkv_b[s * CDIM + col];
                    float b1 = qkv_b[s * CDIM + col + 1];
                    int hh = col >> 5, d = col & 31;
#pragma unroll
                    for (int rh = 0; rh < 2; rh++) {
                        int t = (wid >> 2) * 32 + mt * 16 + (lane >> 2) + rh * 8;
                        float v0 = (acc[mt][nt][2 * rh + 0] + b0) * sc;
                        float v1 = (acc[mt][nt][2 * rh + 1] + b1) * sc;
                        uint32_t off = hh * 4096 + t * 64 +
                                       (((d >> 3) ^ ((t >> 1) & 3)) << 4) + (d & 7) * 2;
                        if (s == 0) {
                            uint32_t hi, lo;
                            split2h(v0, v1, hi, lo);
                            *reinterpret_cast<uint32_t*>(sm + FQ_HI + off) = hi;
                            *reinterpret_cast<uint32_t*>(sm + FQ_LO + off) = lo;
                        } else {
                            uint32_t hv = packh(v0, v1);
                            *reinterpret_cast<uint32_t*>(sm + (s == 1 ? FK : FV) + off) = hv;
                        }
                    }
                }
            }
        }
    }
    __syncthreads();

    // ---------------- Phase 2: attention, 2 teams x 3 iterations ----------------
    const int team = wid >> 2;
    const int wrow = wid & 3;
    const int r0 = wrow * 16 + (lane >> 2);
    const int q2 = (lane & 3) * 2;
    const float* mp = mask + ((size_t)(b & (NMASK - 1)) << 12);

#pragma unroll
    for (int it = 0; it < 3; it++) {
        const int h = 2 * it + team;
        const uint32_t qoff = h * 4096;
        const float* bp = g_bias + ((size_t)h << 12);

        // init S directly with bias + mask
        float S[8][4];
#pragma unroll
        for (int t = 0; t < 8; t++) {
            int cc = 8 * t + q2;
            float2 b0 = *reinterpret_cast<const float2*>(bp + r0 * 64 + cc);
            float2 b1 = *reinterpret_cast<const float2*>(bp + (r0 + 8) * 64 + cc);
            float2 m0 = *reinterpret_cast<const float2*>(mp + r0 * 64 + cc);
            float2 m1 = *reinterpret_cast<const float2*>(mp + (r0 + 8) * 64 + cc);
            S[t][0] = b0.x + m0.x; S[t][1] = b0.y + m0.y;
            S[t][2] = b1.x + m1.x; S[t][3] = b1.y + m1.y;
        }

        // preload K fragments once, Q hi/lo
        const uint32_t qbh = sb + FQ_HI + qoff;
        const uint32_t qbl = sb + FQ_LO + qoff;
        const uint32_t kb  = sb + FK + qoff;
        uint32_t Kf[2][4][4], Qh[2][4], Ql[2][4];
#pragma unroll
        for (int ks = 0; ks < 2; ks++) {
            int qrow = wrow * 16 + ((g & 1) << 3) + rl;
            int qc = (2 * ks + (g >> 1)) ^ ((qrow >> 1) & 3);
            ldsm4(Qh[ks], qbh + qrow * 64 + (qc << 4));
            ldsm4(Ql[ks], qbl + qrow * 64 + (qc << 4));
#pragma unroll
            for (int nt2 = 0; nt2 < 4; nt2++) {
                int row = nt2 * 16 + ((g >> 1) << 3) + rl;
                int c = (2 * ks + (g & 1)) ^ ((row >> 1) & 3);
                ldsm4(Kf[ks][nt2], kb + row * 64 + (c << 4));
            }
        }
#pragma unroll
        for (int ks = 0; ks < 2; ks++)
#pragma unroll
            for (int nt2 = 0; nt2 < 4; nt2++) {
                mma16816(S[2 * nt2],     Qh[ks], Kf[ks][nt2][0], Kf[ks][nt2][1]);
                mma16816(S[2 * nt2 + 1], Qh[ks], Kf[ks][nt2][2], Kf[ks][nt2][3]);
            }
#pragma unroll
        for (int ks = 0; ks < 2; ks++)
#pragma unroll
            for (int nt2 = 0; nt2 < 4; nt2++) {
                mma16816(S[2 * nt2],     Ql[ks], Kf[ks][nt2][0], Kf[ks][nt2][1]);
                mma16816(S[2 * nt2 + 1], Ql[ks], Kf[ks][nt2][2], Kf[ks][nt2][3]);
            }

        // softmax on fragments
        float mlo = -1e30f, mhi = -1e30f;
#pragma unroll
        for (int t = 0; t < 8; t++) {
            mlo = fmaxf(mlo, fmaxf(S[t][0], S[t][1]));
            mhi = fmaxf(mhi, fmaxf(S[t][2], S[t][3]));
        }
#pragma unroll
        for (int off = 1; off < 4; off <<= 1) {
            mlo = fmaxf(mlo, __shfl_xor_sync(0xffffffffu, mlo, off));
            mhi = fmaxf(mhi, __shfl_xor_sync(0xffffffffu, mhi, off));
        }
        float slo = 0.0f, shi = 0.0f;
#pragma unroll
        for (int t = 0; t < 8; t++) {
            S[t][0] = __expf(S[t][0] - mlo); S[t][1] = __expf(S[t][1] - mlo);
            S[t][2] = __expf(S[t][2] - mhi); S[t][3] = __expf(S[t][3] - mhi);
            slo += S[t][0] + S[t][1];
            shi += S[t][2] + S[t][3];
        }
#pragma unroll
        for (int off = 1; off < 4; off <<= 1) {
            slo += __shfl_xor_sync(0xffffffffu, slo, off);
            shi += __shfl_xor_sync(0xffffffffu, shi, off);
        }
        const float ilo = 1.0f / slo, ihi = 1.0f / shi;

        // normalize, write attn, build P fragments (fp16 hi/lo)
        const size_t ab = ((size_t)b * NHEAD + h) << 12;
        uint32_t Ph[4][4], Pl[4][4];
#pragma unroll
        for (int t = 0; t < 8; t++) {
            S[t][0] *= ilo; S[t][1] *= ilo;
            S[t][2] *= ihi; S[t][3] *= ihi;
            *reinterpret_cast<float2*>(attn_out + ab + (size_t)r0 * 64 + 8 * t + q2)
                = make_float2(S[t][0], S[t][1]);
            *reinterpret_cast<float2*>(attn_out + ab + (size_t)(r0 + 8) * 64 + 8 * t + q2)
                = make_float2(S[t][2], S[t][3]);
        }
#pragma unroll
        for (int kt = 0; kt < 4; kt++) {
            split2h(S[2 * kt][0],     S[2 * kt][1],     Ph[kt][0], Pl[kt][0]);
            split2h(S[2 * kt][2],     S[2 * kt][3],     Ph[kt][1], Pl[kt][1]);
            split2h(S[2 * kt + 1][0], S[2 * kt + 1][1], Ph[kt][2], Pl[kt][2]);
            split2h(S[2 * kt + 1][2], S[2 * kt + 1][3], Ph[kt][3], Pl[kt][3]);
        }

        // O = P V: preload V fragments, dense MMA (P hi then lo)
        float O[4][4];
#pragma unroll
        for (int t = 0; t < 4; t++)
#pragma unroll
            for (int j = 0; j < 4; j++) O[t][j] = 0.0f;

        const uint32_t vb = sb + FV + qoff;
        uint32_t Vf[4][2][4];
#pragma unroll
        for (int kt = 0; kt < 4; kt++) {
            int row = kt * 16 + ((g & 1) << 3) + rl;
            int c0 = (0 + (g >> 1)) ^ ((row >> 1) & 3);
            int c1 = (2 + (g >> 1)) ^ ((row >> 1) & 3);
            ldsm4t(Vf[kt][0], vb + row * 64 + (c0 << 4));
            ldsm4t(Vf[kt][1], vb + row * 64 + (c1 << 4));
        }
#pragma unroll
        for (int kt = 0; kt < 4; kt++) {
            mma16816(O[0], Ph[kt], Vf[kt][0][0], Vf[kt][0][1]);
            mma16816(O[1], Ph[kt], Vf[kt][0][2], Vf[kt][0][3]);
            mma16816(O[2], Ph[kt], Vf[kt][1][0], Vf[kt][1][1]);
            mma16816(O[3], Ph[kt], Vf[kt][1][2], Vf[kt][1][3]);
        }
#pragma unroll
        for (int kt = 0; kt < 4; kt++) {
            mma16816(O[0], Pl[kt], Vf[kt][0][0], Vf[kt][0][1]);
            mma16816(O[1], Pl[kt], Vf[kt][0][2], Vf[kt][0][3]);
            mma16816(O[2], Pl[kt], Vf[kt][1][0], Vf[kt][1][1]);
            mma16816(O[3], Pl[kt], Vf[kt][1][2], Vf[kt][1][3]);
        }

        // write O as single fp16, layout [b][tok][h*32+d]
        const size_t ob = (size_t)b * NTOK * CDIM + h * HDIM;
#pragma unroll
        for (int dt = 0; dt < 4; dt++) {
            int col = 8 * dt + q2;
            *reinterpret_cast<uint32_t*>(g_o + ob + (size_t)r0 * CDIM + col)
                = packh(O[dt][0], O[dt][1]);
            *reinterpret_cast<uint32_t*>(g_o + ob + (size_t)(r0 + 8) * CDIM + col)
                = packh(O[dt][2], O[dt][3]);
        }
    }
}

// ---------------- proj GEMM: O (fp16 single) x Wp (fp16 single) ----------------
#define SMA  0
#define SMB  8192
#define GEMM_SMEM 32768

__global__ void __launch_bounds__(256, 2)
proj_gemm(const float* __restrict__ bias, float* __restrict__ out) {
    extern __shared__ char sm[];
    const int tid = threadIdx.x;
    const int wid = tid >> 5, lane = tid & 31;
    const int mBase = blockIdx.y * 64;

    const uint32_t sb = smem_u32(sm);

    float acc[2][6][4];
#pragma unroll
    for (int a = 0; a < 2; a++)
#pragma unroll
        for (int b = 0; b < 6; b++)
#pragma unroll
            for (int c = 0; c < 4; c++) acc[a][b][c] = 0.0f;

    const int g  = lane >> 3, rl = lane & 7;
    const int aRow0 = (wid >> 2) * 32 + ((g & 1) << 3) + rl;
    const int aChG  = g >> 1;
    const int bRow0 = (wid & 3) * 48 + ((g >> 1) << 3) + rl;
    const int bChG  = g & 1;

    for (int kc = 0; kc < 3; kc++) {
        // A: 64 rows x 64 fp16 (single)
#pragma unroll
        for (int i = 0; i < 2; i++) {
            int idx = tid + i * 256;
            int row = idx >> 3, ch = idx & 7;
            size_t src = (size_t)(mBase + row) * CDIM + kc * 64 + ch * 8;
            uint32_t dst = row * 128 + ((ch ^ (row & 7)) << 4);
            *reinterpret_cast<uint4*>(sm + SMA + dst) =
                *reinterpret_cast<const uint4*>(g_o + src);
        }
        // B: 192 rows x 64 fp16 (single)
#pragma unroll
        for (int i = 0; i < 6; i++) {
            int idx = tid + i * 256;
            int row = idx >> 3, ch = idx & 7;
            size_t src = (size_t)row * CDIM + kc * 64 + ch * 8;
            uint32_t dst = row * 128 + ((ch ^ (row & 7)) << 4);
            *reinterpret_cast<uint4*>(sm + SMB + dst) =
                *reinterpret_cast<const uint4*>(g_wp + src);
        }
        __syncthreads();

#pragma unroll
        for (int ks = 0; ks < 4; ks++) {
            uint32_t af[2][4], bf[3][4];
            const int chA = 2 * ks + aChG;
#pragma unroll
            for (int mt = 0; mt < 2; mt++) {
                int row = aRow0 + mt * 16;
                ldsm4(af[mt], sb + SMA + row * 128 + ((chA ^ (row & 7)) << 4));
            }
            const int chB = 2 * ks + bChG;
#pragma unroll
            for (int p = 0; p < 3; p++) {
                int row = bRow0 + p * 16;
                ldsm4(bf[p], sb + SMB + row * 128 + ((chB ^ (row & 7)) << 4));
            }
#pragma unroll
            for (int p = 0; p < 3; p++)
#pragma unroll
                for (int mt = 0; mt < 2; mt++) {
                    mma16816(acc[mt][2 * p],     af[mt], bf[p][0], bf[p][1]);
                    mma16816(acc[mt][2 * p + 1], af[mt], bf[p][2], bf[p][3]);
                }
        }
        __syncthreads();
    }

#pragma unroll
    for (int mt = 0; mt < 2; mt++) {
#pragma unroll
        for (int nt = 0; nt < 6; nt++) {
            int col = (wid & 3) * 48 + nt * 8 + (lane & 3) * 2;
            float b0 = bias[col];
            float b1 = bias[col + 1];
#pragma unroll
            for (int rh = 0; rh < 2; rh++) {
                int t = (wid >> 2) * 32 + mt * 16 + (lane >> 2) + rh * 8;
                float v0 = acc[mt][nt][2 * rh + 0] + b0;
                float v1 = acc[mt][nt][2 * rh + 1] + b1;
                *reinterpret_cast<float2*>(out + (size_t)(mBase + t) * CDIM + col)
                    = make_float2(v0, v1);
            }
        }
    }
}

// ---------------------------------------------------------------------------
extern "C" void kernel_launch(void* const* d_in, const int* in_sizes, int n_in,
                              void* d_out, int out_size) {
    const float* x      = (const float*)d_in[0];
    const float* mask   = (const float*)d_in[1];
    const float* qkv_w  = (const float*)d_in[2];
    const float* qkv_b  = (const float*)d_in[3];
    const float* proj_w = (const float*)d_in[4];
    const float* proj_b = (const float*)d_in[5];
    const float* table  = (const float*)d_in[6];

    float* out = (float*)d_out;
    float* attn_out = out + OUT0_ELEMS;

    cudaFuncSetAttribute(fused_kernel, cudaFuncAttributeMaxDynamicSharedMemorySize, FUSED_SMEM);
    cudaFuncSetAttribute(proj_gemm, cudaFuncAttributeMaxDynamicSharedMemorySize, GEMM_SMEM);

    bias_kernel<<<96, 256>>>(table);
    {
        int w4 = (3 * CDIM * CDIM) / 4;
        convert_kernel<1><<<(w4 + 255) / 256, 256>>>(qkv_w, w4);
        int p4 = (CDIM * CDIM) / 4;
        convert_kernel<2><<<(p4 + 255) / 256, 256>>>(proj_w, p4);
    }

    fused_kernel<<<NWIN, 256, FUSED_SMEM>>>(x, qkv_b, mask, attn_out);
    proj_gemm<<<dim3(1, NWIN), 256, GEMM_SMEM>>>(proj_b, out);

    (void)in_sizes; (void)n_in; (void)out_size;
}